// round 7
// baseline (speedup 1.0000x reference)
#include <cuda_runtime.h>
#include <cuda_bf16.h>
#include <cstdint>

typedef unsigned long long u64;
#define FULLM 0xffffffffu

#define NMAX 50048
__device__ float  g_agg_h[(size_t)NMAX * 64];
__device__ float4 g_sum4[NMAX];
// prepacked h: per node 32 uint2 = [hi 16 uint2 (128B)] [lo 16 uint2 (128B)]
__device__ uint2  g_h2[(size_t)NMAX * 32];

// ===========================================================================
// common helpers
// ===========================================================================
__device__ __forceinline__ uint32_t smem_to_u32(const void* p) {
    uint32_t a;
    asm("{ .reg .u64 t; cvta.to.shared.u64 t, %1; cvt.u32.u64 %0, t; }" : "=r"(a) : "l"(p));
    return a;
}
__device__ __forceinline__ void ldsm4(uint32_t r[4], uint32_t addr) {
    asm volatile("ldmatrix.sync.aligned.m8n8.x4.shared.b16 {%0,%1,%2,%3}, [%4];"
        : "=r"(r[0]), "=r"(r[1]), "=r"(r[2]), "=r"(r[3]) : "r"(addr));
}
__device__ __forceinline__ void mma_bf16(float c[4], const uint32_t a[4],
                                         uint32_t b0, uint32_t b1) {
    asm volatile("mma.sync.aligned.m16n8k16.row.col.f32.bf16.bf16.f32 "
        "{%0,%1,%2,%3},{%4,%5,%6,%7},{%8,%9},{%0,%1,%2,%3};"
        : "+f"(c[0]), "+f"(c[1]), "+f"(c[2]), "+f"(c[3])
        : "r"(a[0]), "r"(a[1]), "r"(a[2]), "r"(a[3]), "r"(b0), "r"(b1));
}
__device__ __forceinline__ void packhl(float a, float b, uint32_t &hi, uint32_t &lo) {
    __nv_bfloat162 hh = __floats2bfloat162_rn(a, b);
    float ra = a - __bfloat162float(hh.x);
    float rb = b - __bfloat162float(hh.y);
    __nv_bfloat162 ll = __floats2bfloat162_rn(ra, rb);
    hi = *(uint32_t*)&hh;
    lo = *(uint32_t*)&ll;
}
__device__ __forceinline__ uint32_t packh(float a, float b) {
    __nv_bfloat162 hh = __floats2bfloat162_rn(a, b);
    return *(uint32_t*)&hh;
}
__device__ __forceinline__ void putw(char* sm, int plane, int j, int k, float x) {
    __nv_bfloat16 hb = __float2bfloat16(x);
    __nv_bfloat16 lb = __float2bfloat16(x - __bfloat162float(hb));
    uint32_t off = (uint32_t)(j * 128 + ((k * 2) ^ ((j & 7) << 4)));
    *(__nv_bfloat16*)(sm + plane + off) = hb;
    *(__nv_bfloat16*)(sm + plane + 8192 + off) = lb;
}
__device__ __forceinline__ void putw_hi(char* sm, int plane, int j, int k, float x) {
    __nv_bfloat16 hb = __float2bfloat16(x);
    uint32_t off = (uint32_t)(j * 128 + ((k * 2) ^ ((j & 7) << 4)));
    *(__nv_bfloat16*)(sm + plane + off) = hb;
}

// ===========================================================================
// Prep + zero kernel: zero accumulators, pack h -> g_h2
// ===========================================================================
__global__ void zero_kernel(const float* __restrict__ h, int n) {
    int stride = gridDim.x * blockDim.x;
    int i0 = blockIdx.x * blockDim.x + threadIdx.x;
    float4 z = make_float4(0.f, 0.f, 0.f, 0.f);
    // zero agg_h (n*16 float4) + sum4 (n float4)
    for (int i = i0; i < n * 17; i += stride) {
        if (i < n * 16) ((float4*)g_agg_h)[i] = z;
        else            g_sum4[i - n * 16] = z;
    }
    // pack h: n*16 float4 chunks -> hi/lo uint2
    const float4* h4 = (const float4*)h;
    for (int i = i0; i < n * 16; i += stride) {
        int node = i >> 4, chunk = i & 15;
        float4 v = h4[i];
        uint32_t h0, l0, h1, l1;
        packhl(v.x, v.y, h0, l0);
        packhl(v.z, v.w, h1, l1);
        g_h2[(size_t)node * 32 + chunk]      = make_uint2(h0, h1);
        g_h2[(size_t)node * 32 + 16 + chunk] = make_uint2(l0, l1);
    }
}

// ===========================================================================
// Edge kernel smem layout
// ===========================================================================
#define ETPB 320
#define EWARPS 10
#define W1A_HI   0
#define W1B_HI   16384
#define W2_HI    32768
#define WC_HI    49152
#define A_OFF    65536                       // per warp 8192 (hi|lo 4096)
#define MISC_OFF (A_OFF + EWARPS * 8192)     // fp32: be1|be2|bc1|wc2|w1rad
#define SMEM_E   (MISC_OFF + 1280)

__global__ __launch_bounds__(ETPB, 1) void edge_mma_kernel(
    const float* __restrict__ coord,
    const int* __restrict__ eidx, int E,
    const float* __restrict__ We1, const float* __restrict__ be1,
    const float* __restrict__ We2, const float* __restrict__ be2,
    const float* __restrict__ Wc1, const float* __restrict__ bc1,
    const float* __restrict__ Wc2, const float* __restrict__ bc2)
{
    extern __shared__ char sm[];
    const uint32_t smb = smem_to_u32(sm);
    const int tid = threadIdx.x;
    float* sMisc = (float*)(sm + MISC_OFF);

    for (int i = tid; i < 129 * 64; i += ETPB) {
        int k = i >> 6, j = i & 63;
        float x = We1[i];
        if (k < 128) putw(sm, (k < 64) ? W1A_HI : W1B_HI, j, k & 63, x);
        else         sMisc[256 + j] = x;
    }
    for (int i = tid; i < 64 * 64; i += ETPB) {
        int k = i >> 6, j = i & 63;
        putw(sm, W2_HI, j, k, We2[i]);
        putw_hi(sm, WC_HI, j, k, Wc1[i]);    // hi-only gate
    }
    if (tid < 64)        sMisc[tid] = be1[tid];
    else if (tid < 128)  sMisc[tid] = be2[tid - 64];
    else if (tid < 192)  sMisc[tid] = bc1[tid - 128];
    else if (tid < 256)  sMisc[tid] = Wc2[tid - 192];
    const float bc2v = bc2[0];
    __syncthreads();

    const int warp = tid >> 5, lane = tid & 31;
    char* aPtr = sm + A_OFF + warp * 8192;
    const uint32_t aHi = smb + A_OFF + warp * 8192;

    const int aRowL = ((lane >> 3) & 1) * 8 + (lane & 7);
    const int aCbL  = ((lane >> 4) & 1) * 16;
    const int bRowL = ((lane >> 4) & 1) * 8 + (lane & 7);
    const int bCbL  = ((lane >> 3) & 1) * 16;
    const int q2 = (lane & 3) * 2;
    const int qr = lane >> 2;

    const int estride = gridDim.x * ETPB;

    for (int e0 = (blockIdx.x * EWARPS + warp) * 32; e0 < E; e0 += estride) {
        int e = e0 + lane;
        bool valid = e < E;
        int ec = valid ? e : (E - 1);
        int r = eidx[ec], cI = eidx[E + ec];
        float dx = coord[r * 3 + 0] - coord[cI * 3 + 0];
        float dy = coord[r * 3 + 1] - coord[cI * 3 + 1];
        float dz = coord[r * 3 + 2] - coord[cI * 3 + 2];
        float rad = valid ? (dx * dx + dy * dy + dz * dz) : 0.f;
        int rI = valid ? r : -1;

        float C[2][8][4];
        #pragma unroll
        for (int m = 0; m < 2; m++)
            #pragma unroll
            for (int n = 0; n < 8; n++)
                #pragma unroll
                for (int k = 0; k < 4; k++) C[m][n][k] = 0.f;

        // ================= GEMM1 =================
        #pragma unroll
        for (int half = 0; half < 2; half++) {
            __syncwarp();
            #pragma unroll
            for (int i = 0; i < 16; i++) {
                int edge = (i << 1) | (lane >> 4);
                int node = __shfl_sync(FULLM, half ? cI : r, edge);
                const uint2* hp = g_h2 + (size_t)node * 32 + (lane & 15);
                uint2 vh = hp[0];
                uint2 vl = hp[16];
                uint32_t off = (uint32_t)(edge * 128 + (((lane & 15) * 8) ^ ((edge & 7) << 4)));
                *(uint2*)(aPtr + off)        = vh;
                *(uint2*)(aPtr + 4096 + off) = vl;
            }
            __syncwarp();

            const uint32_t wB = smb + (half ? W1B_HI : W1A_HI);
            #pragma unroll
            for (int kt = 0; kt < 4; kt++) {
                uint32_t Ah[2][4], Al[2][4];
                #pragma unroll
                for (int m = 0; m < 2; m++) {
                    int ar = m * 16 + aRowL;
                    uint32_t ad = aHi + ar * 128 + ((kt * 32 + aCbL) ^ ((ar & 7) << 4));
                    ldsm4(Ah[m], ad);
                    ldsm4(Al[m], ad + 4096);
                }
                #pragma unroll
                for (int nt2 = 0; nt2 < 4; nt2++) {
                    uint32_t Bh[4], Bl[4];
                    int br = nt2 * 16 + bRowL;
                    uint32_t bd = wB + br * 128 + ((kt * 32 + bCbL) ^ ((br & 7) << 4));
                    ldsm4(Bh, bd);
                    ldsm4(Bl, bd + 8192);
                    #pragma unroll
                    for (int m = 0; m < 2; m++)
                        #pragma unroll
                        for (int p = 0; p < 2; p++) {
                            float* cc = C[m][nt2 * 2 + p];
                            mma_bf16(cc, Ah[m], Bh[2 * p], Bh[2 * p + 1]);
                            mma_bf16(cc, Ah[m], Bl[2 * p], Bl[2 * p + 1]);
                            mma_bf16(cc, Al[m], Bh[2 * p], Bh[2 * p + 1]);
                        }
                }
            }
        }

        // ---- epi1 ----
        uint32_t A2h[2][4][4], A2l[2][4][4];
        #pragma unroll
        for (int m = 0; m < 2; m++) {
            float rad0 = __shfl_sync(FULLM, rad, m * 16 + qr);
            float rad1 = __shfl_sync(FULLM, rad, m * 16 + 8 + qr);
            #pragma unroll
            for (int nt = 0; nt < 8; nt++) {
                int col0 = nt * 8 + q2;
                float2 bb = *(float2*)(sMisc + col0);
                float2 wr = *(float2*)(sMisc + 256 + col0);
                float c0 = fmaxf(C[m][nt][0] + bb.x + rad0 * wr.x, 0.f);
                float c1 = fmaxf(C[m][nt][1] + bb.y + rad0 * wr.y, 0.f);
                float c2 = fmaxf(C[m][nt][2] + bb.x + rad1 * wr.x, 0.f);
                float c3 = fmaxf(C[m][nt][3] + bb.y + rad1 * wr.y, 0.f);
                int kt = nt >> 1, o = (nt & 1) * 2;
                packhl(c0, c1, A2h[m][kt][o],     A2l[m][kt][o]);
                packhl(c2, c3, A2h[m][kt][o + 1], A2l[m][kt][o + 1]);
            }
        }

        // ================= GEMM2 =================
        float C2[2][8][4];
        #pragma unroll
        for (int m = 0; m < 2; m++)
            #pragma unroll
            for (int n = 0; n < 8; n++)
                #pragma unroll
                for (int k = 0; k < 4; k++) C2[m][n][k] = 0.f;
        #pragma unroll
        for (int kt = 0; kt < 4; kt++) {
            #pragma unroll
            for (int nt2 = 0; nt2 < 4; nt2++) {
                uint32_t Bh[4], Bl[4];
                int br = nt2 * 16 + bRowL;
                uint32_t bd = smb + W2_HI + br * 128 + ((kt * 32 + bCbL) ^ ((br & 7) << 4));
                ldsm4(Bh, bd);
                ldsm4(Bl, bd + 8192);
                #pragma unroll
                for (int m = 0; m < 2; m++)
                    #pragma unroll
                    for (int p = 0; p < 2; p++) {
                        float* cc = C2[m][nt2 * 2 + p];
                        mma_bf16(cc, A2h[m][kt], Bh[2 * p], Bh[2 * p + 1]);
                        mma_bf16(cc, A2h[m][kt], Bl[2 * p], Bl[2 * p + 1]);
                        mma_bf16(cc, A2l[m][kt], Bh[2 * p], Bh[2 * p + 1]);
                    }
            }
        }

        // ---- epi2: feat = relu(C2 + be2); float4 atomics via pair exchange ----
        uint32_t A3h[2][4][4];
        #pragma unroll
        for (int m = 0; m < 2; m++) {
            int rr0 = __shfl_sync(FULLM, rI, m * 16 + qr);
            int rr1 = __shfl_sync(FULLM, rI, m * 16 + 8 + qr);
            #pragma unroll
            for (int nt = 0; nt < 8; nt++) {
                int col0 = nt * 8 + q2;
                float2 bb = *(float2*)(sMisc + 64 + col0);
                float f0 = fmaxf(C2[m][nt][0] + bb.x, 0.f);
                float f1 = fmaxf(C2[m][nt][1] + bb.y, 0.f);
                float f2 = fmaxf(C2[m][nt][2] + bb.x, 0.f);
                float f3 = fmaxf(C2[m][nt][3] + bb.y, 0.f);
                int kt = nt >> 1, o = (nt & 1) * 2;
                A3h[m][kt][o]     = packh(f0, f1);
                A3h[m][kt][o + 1] = packh(f2, f3);
                float g0 = __shfl_xor_sync(FULLM, f0, 1);
                float g1 = __shfl_xor_sync(FULLM, f1, 1);
                float g2 = __shfl_xor_sync(FULLM, f2, 1);
                float g3 = __shfl_xor_sync(FULLM, f3, 1);
                if ((lane & 1) == 0) {
                    int cb = nt * 8 + ((lane & 3) >> 1) * 4;
                    if (rr0 >= 0)
                        atomicAdd((float4*)(g_agg_h + (size_t)rr0 * 64 + cb),
                                  make_float4(f0, f1, g0, g1));
                    if (rr1 >= 0)
                        atomicAdd((float4*)(g_agg_h + (size_t)rr1 * 64 + cb),
                                  make_float4(f2, f3, g2, g3));
                }
            }
        }

        // ================= GEMM3 (gate, hi-only) =================
        float C3[2][8][4];
        #pragma unroll
        for (int m = 0; m < 2; m++)
            #pragma unroll
            for (int n = 0; n < 8; n++)
                #pragma unroll
                for (int k = 0; k < 4; k++) C3[m][n][k] = 0.f;
        #pragma unroll
        for (int kt = 0; kt < 4; kt++) {
            #pragma unroll
            for (int nt2 = 0; nt2 < 4; nt2++) {
                uint32_t Bh[4];
                int br = nt2 * 16 + bRowL;
                uint32_t bd = smb + WC_HI + br * 128 + ((kt * 32 + bCbL) ^ ((br & 7) << 4));
                ldsm4(Bh, bd);
                #pragma unroll
                for (int m = 0; m < 2; m++)
                    #pragma unroll
                    for (int p = 0; p < 2; p++)
                        mma_bf16(C3[m][nt2 * 2 + p], A3h[m][kt], Bh[2 * p], Bh[2 * p + 1]);
            }
        }

        // ---- epi3 ----
        #pragma unroll
        for (int m = 0; m < 2; m++) {
            float p0 = 0.f, p1 = 0.f;
            #pragma unroll
            for (int nt = 0; nt < 8; nt++) {
                int col0 = nt * 8 + q2;
                float2 bb = *(float2*)(sMisc + 128 + col0);
                float2 w2 = *(float2*)(sMisc + 192 + col0);
                p0 += fmaxf(C3[m][nt][0] + bb.x, 0.f) * w2.x
                    + fmaxf(C3[m][nt][1] + bb.y, 0.f) * w2.y;
                p1 += fmaxf(C3[m][nt][2] + bb.x, 0.f) * w2.x
                    + fmaxf(C3[m][nt][3] + bb.y, 0.f) * w2.y;
            }
            p0 += __shfl_xor_sync(FULLM, p0, 1);
            p0 += __shfl_xor_sync(FULLM, p0, 2);
            p1 += __shfl_xor_sync(FULLM, p1, 1);
            p1 += __shfl_xor_sync(FULLM, p1, 2);

            int row0 = m * 16 + qr, row1 = row0 + 8;
            float gx0 = __shfl_sync(FULLM, dx, row0), gy0 = __shfl_sync(FULLM, dy, row0),
                  gz0 = __shfl_sync(FULLM, dz, row0);
            float gx1 = __shfl_sync(FULLM, dx, row1), gy1 = __shfl_sync(FULLM, dy, row1),
                  gz1 = __shfl_sync(FULLM, dz, row1);
            int r0v = __shfl_sync(FULLM, rI, row0);
            int r1v = __shfl_sync(FULLM, rI, row1);

            if ((lane & 3) == 0) {
                if (r0v >= 0) {
                    float gt = p0 + bc2v;
                    atomicAdd(&g_sum4[r0v], make_float4(
                        fminf(fmaxf(gx0 * gt, -100.f), 100.f),
                        fminf(fmaxf(gy0 * gt, -100.f), 100.f),
                        fminf(fmaxf(gz0 * gt, -100.f), 100.f), 1.f));
                }
                if (r1v >= 0) {
                    float gt = p1 + bc2v;
                    atomicAdd(&g_sum4[r1v], make_float4(
                        fminf(fmaxf(gx1 * gt, -100.f), 100.f),
                        fminf(fmaxf(gy1 * gt, -100.f), 100.f),
                        fminf(fmaxf(gz1 * gt, -100.f), 100.f), 1.f));
                }
            }
        }
    }
}

// ===========================================================================
// Node kernel: bf16x3 HMMA, warp = 32 nodes x 64 outs; coord fused at head
// ===========================================================================
#define NW1A 0
#define NW1B 16384
#define NW2  32768
#define NMISC 49152
#define NA_OFF 50176
#define SMEM_N (NA_OFF + 8 * 8192)

__global__ __launch_bounds__(256, 1) void node_mma_kernel(
    const float* __restrict__ h,
    const float* __restrict__ Wn1, const float* __restrict__ bn1,
    const float* __restrict__ Wn2, const float* __restrict__ bn2,
    const float* __restrict__ coord, const float* __restrict__ vel,
    float* __restrict__ out_h, float* __restrict__ out_coord,
    float* __restrict__ out_v, int N)
{
    extern __shared__ char sm[];
    const uint32_t smb = smem_to_u32(sm);
    const int tid = threadIdx.x;
    float* sMisc = (float*)(sm + NMISC);

    for (int i = blockIdx.x * 256 + tid; i < N; i += gridDim.x * 256) {
        float4 s = g_sum4[i];
        float c = s.w;
        float invc = (c > 0.f) ? (1.f / fmaxf(c, 1.f)) : 0.f;
        float vx = vel[i * 3 + 0] + s.x * invc * 0.125f;
        float vy = vel[i * 3 + 1] + s.y * invc * 0.125f;
        float vz = vel[i * 3 + 2] + s.z * invc * 0.125f;
        out_v[i * 3 + 0] = vx;
        out_v[i * 3 + 1] = vy;
        out_v[i * 3 + 2] = vz;
        out_coord[i * 3 + 0] = coord[i * 3 + 0] + vx * 0.125f;
        out_coord[i * 3 + 1] = coord[i * 3 + 1] + vy * 0.125f;
        out_coord[i * 3 + 2] = coord[i * 3 + 2] + vz * 0.125f;
    }

    for (int i = tid; i < 128 * 64; i += 256) {
        int k = i >> 6, j = i & 63;
        putw(sm, (k < 64) ? NW1A : NW1B, j, k & 63, Wn1[i]);
    }
    for (int i = tid; i < 64 * 64; i += 256) {
        int k = i >> 6, j = i & 63;
        putw(sm, NW2, j, k, Wn2[i]);
    }
    if (tid < 64)        sMisc[tid] = bn1[tid];
    else if (tid < 128)  sMisc[tid] = bn2[tid - 64];
    __syncthreads();

    const int warp = tid >> 5, lane = tid & 31;
    char* aPtr = sm + NA_OFF + warp * 8192;
    const uint32_t aHi = smb + NA_OFF + warp * 8192;

    const int aRowL = ((lane >> 3) & 1) * 8 + (lane & 7);
    const int aCbL  = ((lane >> 4) & 1) * 16;
    const int bRowL = ((lane >> 4) & 1) * 8 + (lane & 7);
    const int bCbL  = ((lane >> 3) & 1) * 16;
    const int q2 = (lane & 3) * 2;
    const int qr = lane >> 2;

    const int ntiles = (N + 31) >> 5;

    for (int t = blockIdx.x * 8 + warp; t < ntiles; t += gridDim.x * 8) {
        const int nbase = t << 5;

        float C[2][8][4];
        #pragma unroll
        for (int m = 0; m < 2; m++)
            #pragma unroll
            for (int n = 0; n < 8; n++)
                #pragma unroll
                for (int k = 0; k < 4; k++) C[m][n][k] = 0.f;

        #pragma unroll
        for (int half = 0; half < 2; half++) {
            __syncwarp();
            #pragma unroll
            for (int i = 0; i < 16; i++) {
                int row = (i << 1) | (lane >> 4);
                int node = nbase + row;
                if (node >= N) node = N - 1;
                uint32_t off = (uint32_t)(row * 128 + (((lane & 15) * 8) ^ ((row & 7) << 4)));
                if (half == 0) {
                    const uint2* hp = g_h2 + (size_t)node * 32 + (lane & 15);
                    *(uint2*)(aPtr + off)        = hp[0];
                    *(uint2*)(aPtr + 4096 + off) = hp[16];
                } else {
                    float4 v = *(const float4*)(g_agg_h + (size_t)node * 64 + (lane & 15) * 4);
                    uint32_t h0, l0, h1, l1;
                    packhl(v.x, v.y, h0, l0);
                    packhl(v.z, v.w, h1, l1);
                    *(uint2*)(aPtr + off)        = make_uint2(h0, h1);
                    *(uint2*)(aPtr + 4096 + off) = make_uint2(l0, l1);
                }
            }
            __syncwarp();

            const uint32_t wB = smb + (half ? NW1B : NW1A);
            #pragma unroll
            for (int kt = 0; kt < 4; kt++) {
                uint32_t Ah[2][4], Al[2][4];
                #pragma unroll
                for (int m = 0; m < 2; m++) {
                    int ar = m * 16 + aRowL;
                    uint32_t ad = aHi + ar * 128 + ((kt * 32 + aCbL) ^ ((ar & 7) << 4));
                    ldsm4(Ah[m], ad);
                    ldsm4(Al[m], ad + 4096);
                }
                #pragma unroll
                for (int nt2 = 0; nt2 < 4; nt2++) {
                    uint32_t Bh[4], Bl[4];
                    int br = nt2 * 16 + bRowL;
                    uint32_t bd = wB + br * 128 + ((kt * 32 + bCbL) ^ ((br & 7) << 4));
                    ldsm4(Bh, bd);
                    ldsm4(Bl, bd + 8192);
                    #pragma unroll
                    for (int m = 0; m < 2; m++)
                        #pragma unroll
                        for (int p = 0; p < 2; p++) {
                            float* cc = C[m][nt2 * 2 + p];
                            mma_bf16(cc, Ah[m], Bh[2 * p], Bh[2 * p + 1]);
                            mma_bf16(cc, Ah[m], Bl[2 * p], Bl[2 * p + 1]);
                            mma_bf16(cc, Al[m], Bh[2 * p], Bh[2 * p + 1]);
                        }
                }
            }
        }

        uint32_t A2h[2][4][4], A2l[2][4][4];
        #pragma unroll
        for (int m = 0; m < 2; m++) {
            #pragma unroll
            for (int nt = 0; nt < 8; nt++) {
                int col0 = nt * 8 + q2;
                float2 bb = *(float2*)(sMisc + col0);
                float c0 = fmaxf(C[m][nt][0] + bb.x, 0.f);
                float c1 = fmaxf(C[m][nt][1] + bb.y, 0.f);
                float c2 = fmaxf(C[m][nt][2] + bb.x, 0.f);
                float c3 = fmaxf(C[m][nt][3] + bb.y, 0.f);
                int kt = nt >> 1, o = (nt & 1) * 2;
                packhl(c0, c1, A2h[m][kt][o],     A2l[m][kt][o]);
                packhl(c2, c3, A2h[m][kt][o + 1], A2l[m][kt][o + 1]);
            }
        }

        float C2[2][8][4];
        #pragma unroll
        for (int m = 0; m < 2; m++)
            #pragma unroll
            for (int n = 0; n < 8; n++)
                #pragma unroll
                for (int k = 0; k < 4; k++) C2[m][n][k] = 0.f;
        #pragma unroll
        for (int kt = 0; kt < 4; kt++) {
            #pragma unroll
            for (int nt2 = 0; nt2 < 4; nt2++) {
                uint32_t Bh[4], Bl[4];
                int br = nt2 * 16 + bRowL;
                uint32_t bd = smb + NW2 + br * 128 + ((kt * 32 + bCbL) ^ ((br & 7) << 4));
                ldsm4(Bh, bd);
                ldsm4(Bl, bd + 8192);
                #pragma unroll
                for (int m = 0; m < 2; m++)
                    #pragma unroll
                    for (int p = 0; p < 2; p++) {
                        float* cc = C2[m][nt2 * 2 + p];
                        mma_bf16(cc, A2h[m][kt], Bh[2 * p], Bh[2 * p + 1]);
                        mma_bf16(cc, A2h[m][kt], Bl[2 * p], Bl[2 * p + 1]);
                        mma_bf16(cc, A2l[m][kt], Bh[2 * p], Bh[2 * p + 1]);
                    }
            }
        }

        #pragma unroll
        for (int m = 0; m < 2; m++) {
            int row0 = nbase + m * 16 + qr;
            int row1 = row0 + 8;
            bool v0 = row0 < N, v1 = row1 < N;
            #pragma unroll
            for (int nt = 0; nt < 8; nt++) {
                int col0 = nt * 8 + q2;
                float2 bb = *(float2*)(sMisc + 64 + col0);
                if (v0) {
                    float2 rs = *(const float2*)(h + (size_t)row0 * 64 + col0);
                    float2 o = make_float2(C2[m][nt][0] + bb.x + rs.x,
                                           C2[m][nt][1] + bb.y + rs.y);
                    *(float2*)(out_h + (size_t)row0 * 64 + col0) = o;
                }
                if (v1) {
                    float2 rs = *(const float2*)(h + (size_t)row1 * 64 + col0);
                    float2 o = make_float2(C2[m][nt][2] + bb.x + rs.x,
                                           C2[m][nt][3] + bb.y + rs.y);
                    *(float2*)(out_h + (size_t)row1 * 64 + col0) = o;
                }
            }
        }
    }
}

// ---------------------------------------------------------------------------
extern "C" void kernel_launch(void* const* d_in, const int* in_sizes, int n_in,
                              void* d_out, int out_size)
{
    const float* h     = (const float*)d_in[0];
    const float* coord = (const float*)d_in[1];
    const float* vel   = (const float*)d_in[2];
    const int*   eidx  = (const int*)d_in[4];
    const float* We1 = (const float*)d_in[5];
    const float* be1 = (const float*)d_in[6];
    const float* We2 = (const float*)d_in[7];
    const float* be2 = (const float*)d_in[8];
    const float* Wn1 = (const float*)d_in[9];
    const float* bn1 = (const float*)d_in[10];
    const float* Wn2 = (const float*)d_in[11];
    const float* bn2 = (const float*)d_in[12];
    const float* Wc1 = (const float*)d_in[13];
    const float* bc1 = (const float*)d_in[14];
    const float* Wc2 = (const float*)d_in[15];
    const float* bc2 = (const float*)d_in[16];

    const int N = in_sizes[0] / 64;
    const int E = in_sizes[4] / 2;

    float* out       = (float*)d_out;
    float* out_h     = out;
    float* out_coord = out + (size_t)N * 64;
    float* out_v     = out_coord + (size_t)N * 3;

    cudaFuncSetAttribute(edge_mma_kernel, cudaFuncAttributeMaxDynamicSharedMemorySize, SMEM_E);
    cudaFuncSetAttribute(node_mma_kernel, cudaFuncAttributeMaxDynamicSharedMemorySize, SMEM_N);

    zero_kernel<<<512, 256>>>(h, N);
    edge_mma_kernel<<<148, ETPB, SMEM_E>>>(coord, eidx, E,
                                           We1, be1, We2, be2, Wc1, bc1, Wc2, bc2);
    node_mma_kernel<<<148, 256, SMEM_N>>>(h, Wn1, bn1, Wn2, bn2,
                                          coord, vel, out_h, out_coord, out_v, N);
}

// round 8
// speedup vs baseline: 1.3777x; 1.3777x over previous
#include <cuda_runtime.h>
#include <cuda_bf16.h>
#include <cstdint>

typedef unsigned long long u64;
#define FULLM 0xffffffffu

#define NMAX 50048
__device__ float  g_agg_h[(size_t)NMAX * 64];
__device__ float4 g_sum4[NMAX];

// ===========================================================================
// common helpers
// ===========================================================================
__device__ __forceinline__ uint32_t smem_to_u32(const void* p) {
    uint32_t a;
    asm("{ .reg .u64 t; cvta.to.shared.u64 t, %1; cvt.u32.u64 %0, t; }" : "=r"(a) : "l"(p));
    return a;
}
__device__ __forceinline__ void ldsm4(uint32_t r[4], uint32_t addr) {
    asm volatile("ldmatrix.sync.aligned.m8n8.x4.shared.b16 {%0,%1,%2,%3}, [%4];"
        : "=r"(r[0]), "=r"(r[1]), "=r"(r[2]), "=r"(r[3]) : "r"(addr));
}
__device__ __forceinline__ void mma_bf16(float c[4], const uint32_t a[4],
                                         uint32_t b0, uint32_t b1) {
    asm volatile("mma.sync.aligned.m16n8k16.row.col.f32.bf16.bf16.f32 "
        "{%0,%1,%2,%3},{%4,%5,%6,%7},{%8,%9},{%0,%1,%2,%3};"
        : "+f"(c[0]), "+f"(c[1]), "+f"(c[2]), "+f"(c[3])
        : "r"(a[0]), "r"(a[1]), "r"(a[2]), "r"(a[3]), "r"(b0), "r"(b1));
}
__device__ __forceinline__ void packhl(float a, float b, uint32_t &hi, uint32_t &lo) {
    __nv_bfloat162 hh = __floats2bfloat162_rn(a, b);
    float ra = a - __bfloat162float(hh.x);
    float rb = b - __bfloat162float(hh.y);
    __nv_bfloat162 ll = __floats2bfloat162_rn(ra, rb);
    hi = *(uint32_t*)&hh;
    lo = *(uint32_t*)&ll;
}
__device__ __forceinline__ uint32_t packh(float a, float b) {
    __nv_bfloat162 hh = __floats2bfloat162_rn(a, b);
    return *(uint32_t*)&hh;
}
__device__ __forceinline__ void putw(char* sm, int plane, int j, int k, float x) {
    __nv_bfloat16 hb = __float2bfloat16(x);
    __nv_bfloat16 lb = __float2bfloat16(x - __bfloat162float(hb));
    uint32_t off = (uint32_t)(j * 128 + ((k * 2) ^ ((j & 7) << 4)));
    *(__nv_bfloat16*)(sm + plane + off) = hb;
    *(__nv_bfloat16*)(sm + plane + 8192 + off) = lb;
}
__device__ __forceinline__ void putw_hi(char* sm, int plane, int j, int k, float x) {
    __nv_bfloat16 hb = __float2bfloat16(x);
    uint32_t off = (uint32_t)(j * 128 + ((k * 2) ^ ((j & 7) << 4)));
    *(__nv_bfloat16*)(sm + plane + off) = hb;
}

// ===========================================================================
// Edge kernel smem layout
// per-warp A region 16 KB: [row hi 4K | row lo 4K | col hi 4K | col lo 4K]
// ===========================================================================
#define ETPB 288
#define EWARPS 9
#define W1A_HI   0
#define W1B_HI   16384
#define W2_HI    32768
#define WC_HI    49152
#define A_OFF    65536
#define MISC_OFF (A_OFF + EWARPS * 16384)
#define SMEM_E   (MISC_OFF + 1280)

__global__ __launch_bounds__(ETPB, 1) void edge_mma_kernel(
    const float* __restrict__ h, const float* __restrict__ coord,
    const int* __restrict__ eidx, int E,
    const float* __restrict__ We1, const float* __restrict__ be1,
    const float* __restrict__ We2, const float* __restrict__ be2,
    const float* __restrict__ Wc1, const float* __restrict__ bc1,
    const float* __restrict__ Wc2, const float* __restrict__ bc2)
{
    extern __shared__ char sm[];
    const uint32_t smb = smem_to_u32(sm);
    const int tid = threadIdx.x;
    float* sMisc = (float*)(sm + MISC_OFF);

    for (int i = tid; i < 129 * 64; i += ETPB) {
        int k = i >> 6, j = i & 63;
        float x = We1[i];
        if (k < 128) putw(sm, (k < 64) ? W1A_HI : W1B_HI, j, k & 63, x);
        else         sMisc[256 + j] = x;
    }
    for (int i = tid; i < 64 * 64; i += ETPB) {
        int k = i >> 6, j = i & 63;
        putw(sm, W2_HI, j, k, We2[i]);
        putw_hi(sm, WC_HI, j, k, Wc1[i]);    // hi-only gate
    }
    if (tid < 64)        sMisc[tid] = be1[tid];
    else if (tid < 128)  sMisc[tid] = be2[tid - 64];
    else if (tid < 192)  sMisc[tid] = bc1[tid - 128];
    else if (tid < 256)  sMisc[tid] = Wc2[tid - 192];
    const float bc2v = bc2[0];
    __syncthreads();

    const int warp = tid >> 5, lane = tid & 31;
    char* aPtr = sm + A_OFF + warp * 16384;
    const uint32_t aHi = smb + A_OFF + warp * 16384;

    const int aRowL = ((lane >> 3) & 1) * 8 + (lane & 7);
    const int aCbL  = ((lane >> 4) & 1) * 16;
    const int bRowL = ((lane >> 4) & 1) * 8 + (lane & 7);
    const int bCbL  = ((lane >> 3) & 1) * 16;
    const int q2 = (lane & 3) * 2;
    const int qr = lane >> 2;

    const int estride = gridDim.x * ETPB;

    for (int e0 = (blockIdx.x * EWARPS + warp) * 32; e0 < E; e0 += estride) {
        int e = e0 + lane;
        bool valid = e < E;
        int ec = valid ? e : (E - 1);
        int r = eidx[ec], cI = eidx[E + ec];
        float dx = coord[r * 3 + 0] - coord[cI * 3 + 0];
        float dy = coord[r * 3 + 1] - coord[cI * 3 + 1];
        float dz = coord[r * 3 + 2] - coord[cI * 3 + 2];
        float rad = valid ? (dx * dx + dy * dy + dz * dz) : 0.f;
        int rI = valid ? r : -1;

        // ---- gather BOTH halves back-to-back (32 LDG.128 in flight) ----
        __syncwarp();   // previous tile's ldsm reads must finish
        #pragma unroll
        for (int half = 0; half < 2; half++) {
            #pragma unroll
            for (int i = 0; i < 16; i++) {
                int edge = (i << 1) | (lane >> 4);
                int node = __shfl_sync(FULLM, half ? cI : r, edge);
                float4 v = *(const float4*)(h + (size_t)node * 64 + (lane & 15) * 4);
                uint32_t h0, l0, h1, l1;
                packhl(v.x, v.y, h0, l0);
                packhl(v.z, v.w, h1, l1);
                uint32_t off = (uint32_t)(half * 8192 + edge * 128
                              + (((lane & 15) * 8) ^ ((edge & 7) << 4)));
                *(uint2*)(aPtr + off)        = make_uint2(h0, h1);
                *(uint2*)(aPtr + 4096 + off) = make_uint2(l0, l1);
            }
        }
        __syncwarp();

        float C[2][8][4];
        #pragma unroll
        for (int m = 0; m < 2; m++)
            #pragma unroll
            for (int n = 0; n < 8; n++)
                #pragma unroll
                for (int k = 0; k < 4; k++) C[m][n][k] = 0.f;

        // ================= GEMM1 (both halves) =================
        #pragma unroll
        for (int half = 0; half < 2; half++) {
            const uint32_t aBase = aHi + half * 8192;
            const uint32_t wB = smb + (half ? W1B_HI : W1A_HI);
            #pragma unroll
            for (int kt = 0; kt < 4; kt++) {
                uint32_t Ah[2][4], Al[2][4];
                #pragma unroll
                for (int m = 0; m < 2; m++) {
                    int ar = m * 16 + aRowL;
                    uint32_t ad = aBase + ar * 128 + ((kt * 32 + aCbL) ^ ((ar & 7) << 4));
                    ldsm4(Ah[m], ad);
                    ldsm4(Al[m], ad + 4096);
                }
                #pragma unroll
                for (int nt2 = 0; nt2 < 4; nt2++) {
                    uint32_t Bh[4], Bl[4];
                    int br = nt2 * 16 + bRowL;
                    uint32_t bd = wB + br * 128 + ((kt * 32 + bCbL) ^ ((br & 7) << 4));
                    ldsm4(Bh, bd);
                    ldsm4(Bl, bd + 8192);
                    #pragma unroll
                    for (int m = 0; m < 2; m++)
                        #pragma unroll
                        for (int p = 0; p < 2; p++) {
                            float* cc = C[m][nt2 * 2 + p];
                            mma_bf16(cc, Ah[m], Bh[2 * p], Bh[2 * p + 1]);
                            mma_bf16(cc, Ah[m], Bl[2 * p], Bl[2 * p + 1]);
                            mma_bf16(cc, Al[m], Bh[2 * p], Bh[2 * p + 1]);
                        }
                }
            }
        }

        // ---- epi1 ----
        uint32_t A2h[2][4][4], A2l[2][4][4];
        #pragma unroll
        for (int m = 0; m < 2; m++) {
            float rad0 = __shfl_sync(FULLM, rad, m * 16 + qr);
            float rad1 = __shfl_sync(FULLM, rad, m * 16 + 8 + qr);
            #pragma unroll
            for (int nt = 0; nt < 8; nt++) {
                int col0 = nt * 8 + q2;
                float2 bb = *(float2*)(sMisc + col0);
                float2 wr = *(float2*)(sMisc + 256 + col0);
                float c0 = fmaxf(C[m][nt][0] + bb.x + rad0 * wr.x, 0.f);
                float c1 = fmaxf(C[m][nt][1] + bb.y + rad0 * wr.y, 0.f);
                float c2 = fmaxf(C[m][nt][2] + bb.x + rad1 * wr.x, 0.f);
                float c3 = fmaxf(C[m][nt][3] + bb.y + rad1 * wr.y, 0.f);
                int kt = nt >> 1, o = (nt & 1) * 2;
                packhl(c0, c1, A2h[m][kt][o],     A2l[m][kt][o]);
                packhl(c2, c3, A2h[m][kt][o + 1], A2l[m][kt][o + 1]);
            }
        }

        // ================= GEMM2 =================
        float C2[2][8][4];
        #pragma unroll
        for (int m = 0; m < 2; m++)
            #pragma unroll
            for (int n = 0; n < 8; n++)
                #pragma unroll
                for (int k = 0; k < 4; k++) C2[m][n][k] = 0.f;
        #pragma unroll
        for (int kt = 0; kt < 4; kt++) {
            #pragma unroll
            for (int nt2 = 0; nt2 < 4; nt2++) {
                uint32_t Bh[4], Bl[4];
                int br = nt2 * 16 + bRowL;
                uint32_t bd = smb + W2_HI + br * 128 + ((kt * 32 + bCbL) ^ ((br & 7) << 4));
                ldsm4(Bh, bd);
                ldsm4(Bl, bd + 8192);
                #pragma unroll
                for (int m = 0; m < 2; m++)
                    #pragma unroll
                    for (int p = 0; p < 2; p++) {
                        float* cc = C2[m][nt2 * 2 + p];
                        mma_bf16(cc, A2h[m][kt], Bh[2 * p], Bh[2 * p + 1]);
                        mma_bf16(cc, A2h[m][kt], Bl[2 * p], Bl[2 * p + 1]);
                        mma_bf16(cc, A2l[m][kt], Bh[2 * p], Bh[2 * p + 1]);
                    }
            }
        }

        // ---- epi2: feat = relu(C2 + be2); float4 atomics via pair exchange ----
        uint32_t A3h[2][4][4];
        #pragma unroll
        for (int m = 0; m < 2; m++) {
            int rr0 = __shfl_sync(FULLM, rI, m * 16 + qr);
            int rr1 = __shfl_sync(FULLM, rI, m * 16 + 8 + qr);
            #pragma unroll
            for (int nt = 0; nt < 8; nt++) {
                int col0 = nt * 8 + q2;
                float2 bb = *(float2*)(sMisc + 64 + col0);
                float f0 = fmaxf(C2[m][nt][0] + bb.x, 0.f);
                float f1 = fmaxf(C2[m][nt][1] + bb.y, 0.f);
                float f2 = fmaxf(C2[m][nt][2] + bb.x, 0.f);
                float f3 = fmaxf(C2[m][nt][3] + bb.y, 0.f);
                int kt = nt >> 1, o = (nt & 1) * 2;
                A3h[m][kt][o]     = packh(f0, f1);
                A3h[m][kt][o + 1] = packh(f2, f3);
                float g0 = __shfl_xor_sync(FULLM, f0, 1);
                float g1 = __shfl_xor_sync(FULLM, f1, 1);
                float g2 = __shfl_xor_sync(FULLM, f2, 1);
                float g3 = __shfl_xor_sync(FULLM, f3, 1);
                if ((lane & 1) == 0) {
                    int cb = nt * 8 + ((lane & 3) >> 1) * 4;
                    if (rr0 >= 0)
                        atomicAdd((float4*)(g_agg_h + (size_t)rr0 * 64 + cb),
                                  make_float4(f0, f1, g0, g1));
                    if (rr1 >= 0)
                        atomicAdd((float4*)(g_agg_h + (size_t)rr1 * 64 + cb),
                                  make_float4(f2, f3, g2, g3));
                }
            }
        }

        // ================= GEMM3 (gate, hi-only) =================
        float C3[2][8][4];
        #pragma unroll
        for (int m = 0; m < 2; m++)
            #pragma unroll
            for (int n = 0; n < 8; n++)
                #pragma unroll
                for (int k = 0; k < 4; k++) C3[m][n][k] = 0.f;
        #pragma unroll
        for (int kt = 0; kt < 4; kt++) {
            #pragma unroll
            for (int nt2 = 0; nt2 < 4; nt2++) {
                uint32_t Bh[4];
                int br = nt2 * 16 + bRowL;
                uint32_t bd = smb + WC_HI + br * 128 + ((kt * 32 + bCbL) ^ ((br & 7) << 4));
                ldsm4(Bh, bd);
                #pragma unroll
                for (int m = 0; m < 2; m++)
                    #pragma unroll
                    for (int p = 0; p < 2; p++)
                        mma_bf16(C3[m][nt2 * 2 + p], A3h[m][kt], Bh[2 * p], Bh[2 * p + 1]);
            }
        }

        // ---- epi3 ----
        #pragma unroll
        for (int m = 0; m < 2; m++) {
            float p0 = 0.f, p1 = 0.f;
            #pragma unroll
            for (int nt = 0; nt < 8; nt++) {
                int col0 = nt * 8 + q2;
                float2 bb = *(float2*)(sMisc + 128 + col0);
                float2 w2 = *(float2*)(sMisc + 192 + col0);
                p0 += fmaxf(C3[m][nt][0] + bb.x, 0.f) * w2.x
                    + fmaxf(C3[m][nt][1] + bb.y, 0.f) * w2.y;
                p1 += fmaxf(C3[m][nt][2] + bb.x, 0.f) * w2.x
                    + fmaxf(C3[m][nt][3] + bb.y, 0.f) * w2.y;
            }
            p0 += __shfl_xor_sync(FULLM, p0, 1);
            p0 += __shfl_xor_sync(FULLM, p0, 2);
            p1 += __shfl_xor_sync(FULLM, p1, 1);
            p1 += __shfl_xor_sync(FULLM, p1, 2);

            int row0 = m * 16 + qr, row1 = row0 + 8;
            float gx0 = __shfl_sync(FULLM, dx, row0), gy0 = __shfl_sync(FULLM, dy, row0),
                  gz0 = __shfl_sync(FULLM, dz, row0);
            float gx1 = __shfl_sync(FULLM, dx, row1), gy1 = __shfl_sync(FULLM, dy, row1),
                  gz1 = __shfl_sync(FULLM, dz, row1);
            int r0v = __shfl_sync(FULLM, rI, row0);
            int r1v = __shfl_sync(FULLM, rI, row1);

            if ((lane & 3) == 0) {
                if (r0v >= 0) {
                    float gt = p0 + bc2v;
                    atomicAdd(&g_sum4[r0v], make_float4(
                        fminf(fmaxf(gx0 * gt, -100.f), 100.f),
                        fminf(fmaxf(gy0 * gt, -100.f), 100.f),
                        fminf(fmaxf(gz0 * gt, -100.f), 100.f), 1.f));
                }
                if (r1v >= 0) {
                    float gt = p1 + bc2v;
                    atomicAdd(&g_sum4[r1v], make_float4(
                        fminf(fmaxf(gx1 * gt, -100.f), 100.f),
                        fminf(fmaxf(gy1 * gt, -100.f), 100.f),
                        fminf(fmaxf(gz1 * gt, -100.f), 100.f), 1.f));
                }
            }
        }
    }
}

// ===========================================================================
// Node kernel: bf16x3 HMMA, warp = 32 nodes x 64 outs; coord fused at head
// ===========================================================================
#define NW1A 0
#define NW1B 16384
#define NW2  32768
#define NMISC 49152
#define NA_OFF 50176
#define SMEM_N (NA_OFF + 8 * 8192)

__global__ __launch_bounds__(256, 1) void node_mma_kernel(
    const float* __restrict__ h,
    const float* __restrict__ Wn1, const float* __restrict__ bn1,
    const float* __restrict__ Wn2, const float* __restrict__ bn2,
    const float* __restrict__ coord, const float* __restrict__ vel,
    float* __restrict__ out_h, float* __restrict__ out_coord,
    float* __restrict__ out_v, int N)
{
    extern __shared__ char sm[];
    const uint32_t smb = smem_to_u32(sm);
    const int tid = threadIdx.x;
    float* sMisc = (float*)(sm + NMISC);

    for (int i = blockIdx.x * 256 + tid; i < N; i += gridDim.x * 256) {
        float4 s = g_sum4[i];
        float c = s.w;
        float invc = (c > 0.f) ? (1.f / fmaxf(c, 1.f)) : 0.f;
        float vx = vel[i * 3 + 0] + s.x * invc * 0.125f;
        float vy = vel[i * 3 + 1] + s.y * invc * 0.125f;
        float vz = vel[i * 3 + 2] + s.z * invc * 0.125f;
        out_v[i * 3 + 0] = vx;
        out_v[i * 3 + 1] = vy;
        out_v[i * 3 + 2] = vz;
        out_coord[i * 3 + 0] = coord[i * 3 + 0] + vx * 0.125f;
        out_coord[i * 3 + 1] = coord[i * 3 + 1] + vy * 0.125f;
        out_coord[i * 3 + 2] = coord[i * 3 + 2] + vz * 0.125f;
    }

    for (int i = tid; i < 128 * 64; i += 256) {
        int k = i >> 6, j = i & 63;
        putw(sm, (k < 64) ? NW1A : NW1B, j, k & 63, Wn1[i]);
    }
    for (int i = tid; i < 64 * 64; i += 256) {
        int k = i >> 6, j = i & 63;
        putw(sm, NW2, j, k, Wn2[i]);
    }
    if (tid < 64)        sMisc[tid] = bn1[tid];
    else if (tid < 128)  sMisc[tid] = bn2[tid - 64];
    __syncthreads();

    const int warp = tid >> 5, lane = tid & 31;
    char* aPtr = sm + NA_OFF + warp * 8192;
    const uint32_t aHi = smb + NA_OFF + warp * 8192;

    const int aRowL = ((lane >> 3) & 1) * 8 + (lane & 7);
    const int aCbL  = ((lane >> 4) & 1) * 16;
    const int bRowL = ((lane >> 4) & 1) * 8 + (lane & 7);
    const int bCbL  = ((lane >> 3) & 1) * 16;
    const int q2 = (lane & 3) * 2;
    const int qr = lane >> 2;

    const int ntiles = (N + 31) >> 5;

    for (int t = blockIdx.x * 8 + warp; t < ntiles; t += gridDim.x * 8) {
        const int nbase = t << 5;

        float C[2][8][4];
        #pragma unroll
        for (int m = 0; m < 2; m++)
            #pragma unroll
            for (int n = 0; n < 8; n++)
                #pragma unroll
                for (int k = 0; k < 4; k++) C[m][n][k] = 0.f;

        #pragma unroll
        for (int half = 0; half < 2; half++) {
            __syncwarp();
            const float* src = half ? g_agg_h : h;
            #pragma unroll
            for (int i = 0; i < 16; i++) {
                int row = (i << 1) | (lane >> 4);
                int node = nbase + row;
                if (node >= N) node = N - 1;
                float4 v = *(const float4*)(src + (size_t)node * 64 + (lane & 15) * 4);
                uint32_t h0, l0, h1, l1;
                packhl(v.x, v.y, h0, l0);
                packhl(v.z, v.w, h1, l1);
                uint32_t off = (uint32_t)(row * 128 + (((lane & 15) * 8) ^ ((row & 7) << 4)));
                *(uint2*)(aPtr + off)        = make_uint2(h0, h1);
                *(uint2*)(aPtr + 4096 + off) = make_uint2(l0, l1);
            }
            __syncwarp();

            const uint32_t wB = smb + (half ? NW1B : NW1A);
            #pragma unroll
            for (int kt = 0; kt < 4; kt++) {
                uint32_t Ah[2][4], Al[2][4];
                #pragma unroll
                for (int m = 0; m < 2; m++) {
                    int ar = m * 16 + aRowL;
                    uint32_t ad = aHi + ar * 128 + ((kt * 32 + aCbL) ^ ((ar & 7) << 4));
                    ldsm4(Ah[m], ad);
                    ldsm4(Al[m], ad + 4096);
                }
                #pragma unroll
                for (int nt2 = 0; nt2 < 4; nt2++) {
                    uint32_t Bh[4], Bl[4];
                    int br = nt2 * 16 + bRowL;
                    uint32_t bd = wB + br * 128 + ((kt * 32 + bCbL) ^ ((br & 7) << 4));
                    ldsm4(Bh, bd);
                    ldsm4(Bl, bd + 8192);
                    #pragma unroll
                    for (int m = 0; m < 2; m++)
                        #pragma unroll
                        for (int p = 0; p < 2; p++) {
                            float* cc = C[m][nt2 * 2 + p];
                            mma_bf16(cc, Ah[m], Bh[2 * p], Bh[2 * p + 1]);
                            mma_bf16(cc, Ah[m], Bl[2 * p], Bl[2 * p + 1]);
                            mma_bf16(cc, Al[m], Bh[2 * p], Bh[2 * p + 1]);
                        }
                }
            }
        }

        uint32_t A2h[2][4][4], A2l[2][4][4];
        #pragma unroll
        for (int m = 0; m < 2; m++) {
            #pragma unroll
            for (int nt = 0; nt < 8; nt++) {
                int col0 = nt * 8 + q2;
                float2 bb = *(float2*)(sMisc + col0);
                float c0 = fmaxf(C[m][nt][0] + bb.x, 0.f);
                float c1 = fmaxf(C[m][nt][1] + bb.y, 0.f);
                float c2 = fmaxf(C[m][nt][2] + bb.x, 0.f);
                float c3 = fmaxf(C[m][nt][3] + bb.y, 0.f);
                int kt = nt >> 1, o = (nt & 1) * 2;
                packhl(c0, c1, A2h[m][kt][o],     A2l[m][kt][o]);
                packhl(c2, c3, A2h[m][kt][o + 1], A2l[m][kt][o + 1]);
            }
        }

        float C2[2][8][4];
        #pragma unroll
        for (int m = 0; m < 2; m++)
            #pragma unroll
            for (int n = 0; n < 8; n++)
                #pragma unroll
                for (int k = 0; k < 4; k++) C2[m][n][k] = 0.f;
        #pragma unroll
        for (int kt = 0; kt < 4; kt++) {
            #pragma unroll
            for (int nt2 = 0; nt2 < 4; nt2++) {
                uint32_t Bh[4], Bl[4];
                int br = nt2 * 16 + bRowL;
                uint32_t bd = smb + NW2 + br * 128 + ((kt * 32 + bCbL) ^ ((br & 7) << 4));
                ldsm4(Bh, bd);
                ldsm4(Bl, bd + 8192);
                #pragma unroll
                for (int m = 0; m < 2; m++)
                    #pragma unroll
                    for (int p = 0; p < 2; p++) {
                        float* cc = C2[m][nt2 * 2 + p];
                        mma_bf16(cc, A2h[m][kt], Bh[2 * p], Bh[2 * p + 1]);
                        mma_bf16(cc, A2h[m][kt], Bl[2 * p], Bl[2 * p + 1]);
                        mma_bf16(cc, A2l[m][kt], Bh[2 * p], Bh[2 * p + 1]);
                    }
            }
        }

        #pragma unroll
        for (int m = 0; m < 2; m++) {
            int row0 = nbase + m * 16 + qr;
            int row1 = row0 + 8;
            bool v0 = row0 < N, v1 = row1 < N;
            #pragma unroll
            for (int nt = 0; nt < 8; nt++) {
                int col0 = nt * 8 + q2;
                float2 bb = *(float2*)(sMisc + 64 + col0);
                if (v0) {
                    float2 rs = *(const float2*)(h + (size_t)row0 * 64 + col0);
                    float2 o = make_float2(C2[m][nt][0] + bb.x + rs.x,
                                           C2[m][nt][1] + bb.y + rs.y);
                    *(float2*)(out_h + (size_t)row0 * 64 + col0) = o;
                }
                if (v1) {
                    float2 rs = *(const float2*)(h + (size_t)row1 * 64 + col0);
                    float2 o = make_float2(C2[m][nt][2] + bb.x + rs.x,
                                           C2[m][nt][3] + bb.y + rs.y);
                    *(float2*)(out_h + (size_t)row1 * 64 + col0) = o;
                }
            }
        }
    }
}

// ---------------------------------------------------------------------------
__global__ void zero_kernel(int n) {
    int total = n * 17;
    int stride = gridDim.x * blockDim.x;
    float4 z = make_float4(0.f, 0.f, 0.f, 0.f);
    for (int i = blockIdx.x * blockDim.x + threadIdx.x; i < total; i += stride) {
        if (i < n * 16) ((float4*)g_agg_h)[i] = z;
        else            g_sum4[i - n * 16] = z;
    }
}

// ---------------------------------------------------------------------------
extern "C" void kernel_launch(void* const* d_in, const int* in_sizes, int n_in,
                              void* d_out, int out_size)
{
    const float* h     = (const float*)d_in[0];
    const float* coord = (const float*)d_in[1];
    const float* vel   = (const float*)d_in[2];
    const int*   eidx  = (const int*)d_in[4];
    const float* We1 = (const float*)d_in[5];
    const float* be1 = (const float*)d_in[6];
    const float* We2 = (const float*)d_in[7];
    const float* be2 = (const float*)d_in[8];
    const float* Wn1 = (const float*)d_in[9];
    const float* bn1 = (const float*)d_in[10];
    const float* Wn2 = (const float*)d_in[11];
    const float* bn2 = (const float*)d_in[12];
    const float* Wc1 = (const float*)d_in[13];
    const float* bc1 = (const float*)d_in[14];
    const float* Wc2 = (const float*)d_in[15];
    const float* bc2 = (const float*)d_in[16];

    const int N = in_sizes[0] / 64;
    const int E = in_sizes[4] / 2;

    float* out       = (float*)d_out;
    float* out_h     = out;
    float* out_coord = out + (size_t)N * 64;
    float* out_v     = out_coord + (size_t)N * 3;

    cudaFuncSetAttribute(edge_mma_kernel, cudaFuncAttributeMaxDynamicSharedMemorySize, SMEM_E);
    cudaFuncSetAttribute(node_mma_kernel, cudaFuncAttributeMaxDynamicSharedMemorySize, SMEM_N);

    zero_kernel<<<512, 256>>>(N);
    edge_mma_kernel<<<148, ETPB, SMEM_E>>>(h, coord, eidx, E,
                                           We1, be1, We2, be2, Wc1, bc1, Wc2, bc2);
    node_mma_kernel<<<148, 256, SMEM_N>>>(h, Wn1, bn1, Wn2, bn2,
                                          coord, vel, out_h, out_coord, out_v, N);
}

// round 9
// speedup vs baseline: 1.5195x; 1.1029x over previous
#include <cuda_runtime.h>
#include <cuda_bf16.h>
#include <cstdint>

typedef unsigned long long u64;
#define FULLM 0xffffffffu

#define NMAX 50048
__device__ float  g_agg_h[(size_t)NMAX * 64];
__device__ float4 g_sum4[NMAX];

// ===========================================================================
// common helpers
// ===========================================================================
__device__ __forceinline__ uint32_t smem_to_u32(const void* p) {
    uint32_t a;
    asm("{ .reg .u64 t; cvta.to.shared.u64 t, %1; cvt.u32.u64 %0, t; }" : "=r"(a) : "l"(p));
    return a;
}
__device__ __forceinline__ void ldsm4(uint32_t r[4], uint32_t addr) {
    asm volatile("ldmatrix.sync.aligned.m8n8.x4.shared.b16 {%0,%1,%2,%3}, [%4];"
        : "=r"(r[0]), "=r"(r[1]), "=r"(r[2]), "=r"(r[3]) : "r"(addr));
}
__device__ __forceinline__ void mma_bf16(float c[4], const uint32_t a[4],
                                         uint32_t b0, uint32_t b1) {
    asm volatile("mma.sync.aligned.m16n8k16.row.col.f32.bf16.bf16.f32 "
        "{%0,%1,%2,%3},{%4,%5,%6,%7},{%8,%9},{%0,%1,%2,%3};"
        : "+f"(c[0]), "+f"(c[1]), "+f"(c[2]), "+f"(c[3])
        : "r"(a[0]), "r"(a[1]), "r"(a[2]), "r"(a[3]), "r"(b0), "r"(b1));
}
__device__ __forceinline__ void packhl(float a, float b, uint32_t &hi, uint32_t &lo) {
    __nv_bfloat162 hh = __floats2bfloat162_rn(a, b);
    float ra = a - __bfloat162float(hh.x);
    float rb = b - __bfloat162float(hh.y);
    __nv_bfloat162 ll = __floats2bfloat162_rn(ra, rb);
    hi = *(uint32_t*)&hh;
    lo = *(uint32_t*)&ll;
}
__device__ __forceinline__ uint32_t packh(float a, float b) {
    __nv_bfloat162 hh = __floats2bfloat162_rn(a, b);
    return *(uint32_t*)&hh;
}
__device__ __forceinline__ void putw(char* sm, int plane, int j, int k, float x) {
    __nv_bfloat16 hb = __float2bfloat16(x);
    __nv_bfloat16 lb = __float2bfloat16(x - __bfloat162float(hb));
    uint32_t off = (uint32_t)(j * 128 + ((k * 2) ^ ((j & 7) << 4)));
    *(__nv_bfloat16*)(sm + plane + off) = hb;
    *(__nv_bfloat16*)(sm + plane + 8192 + off) = lb;
}
__device__ __forceinline__ void putw_hi(char* sm, int plane, int j, int k, float x) {
    __nv_bfloat16 hb = __float2bfloat16(x);
    uint32_t off = (uint32_t)(j * 128 + ((k * 2) ^ ((j & 7) << 4)));
    *(__nv_bfloat16*)(sm + plane + off) = hb;
}

// ===========================================================================
// Edge kernel smem layout (R6-proven: 10 warps, 8 KB/warp, per-half gather)
// ===========================================================================
#define ETPB 320
#define EWARPS 10
#define W1A_HI   0
#define W1B_HI   16384
#define W2_HI    32768
#define WC_HI    49152
#define A_OFF    65536                       // per warp 8192 (hi|lo 4096)
#define MISC_OFF (A_OFF + EWARPS * 8192)     // fp32: be1|be2|bc1|wc2|w1rad
#define SMEM_E   (MISC_OFF + 1280)

__global__ __launch_bounds__(ETPB, 1) void edge_mma_kernel(
    const float* __restrict__ h, const float* __restrict__ coord,
    const int* __restrict__ eidx, int E,
    const float* __restrict__ We1, const float* __restrict__ be1,
    const float* __restrict__ We2, const float* __restrict__ be2,
    const float* __restrict__ Wc1, const float* __restrict__ bc1,
    const float* __restrict__ Wc2, const float* __restrict__ bc2)
{
    extern __shared__ char sm[];
    const uint32_t smb = smem_to_u32(sm);
    const int tid = threadIdx.x;
    float* sMisc = (float*)(sm + MISC_OFF);

    for (int i = tid; i < 129 * 64; i += ETPB) {
        int k = i >> 6, j = i & 63;
        float x = We1[i];
        if (k < 128) putw(sm, (k < 64) ? W1A_HI : W1B_HI, j, k & 63, x);
        else         sMisc[256 + j] = x;
    }
    for (int i = tid; i < 64 * 64; i += ETPB) {
        int k = i >> 6, j = i & 63;
        putw(sm, W2_HI, j, k, We2[i]);
        putw_hi(sm, WC_HI, j, k, Wc1[i]);    // hi-only gate
    }
    if (tid < 64)        sMisc[tid] = be1[tid];
    else if (tid < 128)  sMisc[tid] = be2[tid - 64];
    else if (tid < 192)  sMisc[tid] = bc1[tid - 128];
    else if (tid < 256)  sMisc[tid] = Wc2[tid - 192];
    const float bc2v = bc2[0];
    __syncthreads();

    const int warp = tid >> 5, lane = tid & 31;
    char* aPtr = sm + A_OFF + warp * 8192;
    const uint32_t aHi = smb + A_OFF + warp * 8192;

    const int aRowL = ((lane >> 3) & 1) * 8 + (lane & 7);
    const int aCbL  = ((lane >> 4) & 1) * 16;
    const int bRowL = ((lane >> 4) & 1) * 8 + (lane & 7);
    const int bCbL  = ((lane >> 3) & 1) * 16;
    const int q2 = (lane & 3) * 2;
    const int qr = lane >> 2;

    const int estride = gridDim.x * ETPB;

    for (int e0 = (blockIdx.x * EWARPS + warp) * 32; e0 < E; e0 += estride) {
        int e = e0 + lane;
        bool valid = e < E;
        int ec = valid ? e : (E - 1);
        int r = eidx[ec], cI = eidx[E + ec];
        float dx = coord[r * 3 + 0] - coord[cI * 3 + 0];
        float dy = coord[r * 3 + 1] - coord[cI * 3 + 1];
        float dz = coord[r * 3 + 2] - coord[cI * 3 + 2];
        float rad = valid ? (dx * dx + dy * dy + dz * dz) : 0.f;
        int rI = valid ? r : -1;

        float C[2][8][4];
        #pragma unroll
        for (int m = 0; m < 2; m++)
            #pragma unroll
            for (int n = 0; n < 8; n++)
                #pragma unroll
                for (int k = 0; k < 4; k++) C[m][n][k] = 0.f;

        // ================= GEMM1 =================
        #pragma unroll
        for (int half = 0; half < 2; half++) {
            __syncwarp();
            #pragma unroll
            for (int i = 0; i < 16; i++) {
                int edge = (i << 1) | (lane >> 4);
                int node = __shfl_sync(FULLM, half ? cI : r, edge);
                float4 v = *(const float4*)(h + (size_t)node * 64 + (lane & 15) * 4);
                uint32_t h0, l0, h1, l1;
                packhl(v.x, v.y, h0, l0);
                packhl(v.z, v.w, h1, l1);
                uint32_t off = (uint32_t)(edge * 128 + (((lane & 15) * 8) ^ ((edge & 7) << 4)));
                *(uint2*)(aPtr + off)        = make_uint2(h0, h1);
                *(uint2*)(aPtr + 4096 + off) = make_uint2(l0, l1);
            }
            __syncwarp();

            const uint32_t wB = smb + (half ? W1B_HI : W1A_HI);
            #pragma unroll
            for (int kt = 0; kt < 4; kt++) {
                uint32_t Ah[2][4], Al[2][4];
                #pragma unroll
                for (int m = 0; m < 2; m++) {
                    int ar = m * 16 + aRowL;
                    uint32_t ad = aHi + ar * 128 + ((kt * 32 + aCbL) ^ ((ar & 7) << 4));
                    ldsm4(Ah[m], ad);
                    ldsm4(Al[m], ad + 4096);
                }
                #pragma unroll
                for (int nt2 = 0; nt2 < 4; nt2++) {
                    uint32_t Bh[4], Bl[4];
                    int br = nt2 * 16 + bRowL;
                    uint32_t bd = wB + br * 128 + ((kt * 32 + bCbL) ^ ((br & 7) << 4));
                    ldsm4(Bh, bd);
                    ldsm4(Bl, bd + 8192);
                    #pragma unroll
                    for (int m = 0; m < 2; m++)
                        #pragma unroll
                        for (int p = 0; p < 2; p++) {
                            float* cc = C[m][nt2 * 2 + p];
                            mma_bf16(cc, Ah[m], Bh[2 * p], Bh[2 * p + 1]);
                            mma_bf16(cc, Ah[m], Bl[2 * p], Bl[2 * p + 1]);
                            mma_bf16(cc, Al[m], Bh[2 * p], Bh[2 * p + 1]);
                        }
                }
            }
        }

        // ---- epi1 ----
        uint32_t A2h[2][4][4], A2l[2][4][4];
        #pragma unroll
        for (int m = 0; m < 2; m++) {
            float rad0 = __shfl_sync(FULLM, rad, m * 16 + qr);
            float rad1 = __shfl_sync(FULLM, rad, m * 16 + 8 + qr);
            #pragma unroll
            for (int nt = 0; nt < 8; nt++) {
                int col0 = nt * 8 + q2;
                float2 bb = *(float2*)(sMisc + col0);
                float2 wr = *(float2*)(sMisc + 256 + col0);
                float c0 = fmaxf(C[m][nt][0] + bb.x + rad0 * wr.x, 0.f);
                float c1 = fmaxf(C[m][nt][1] + bb.y + rad0 * wr.y, 0.f);
                float c2 = fmaxf(C[m][nt][2] + bb.x + rad1 * wr.x, 0.f);
                float c3 = fmaxf(C[m][nt][3] + bb.y + rad1 * wr.y, 0.f);
                int kt = nt >> 1, o = (nt & 1) * 2;
                packhl(c0, c1, A2h[m][kt][o],     A2l[m][kt][o]);
                packhl(c2, c3, A2h[m][kt][o + 1], A2l[m][kt][o + 1]);
            }
        }

        // ================= GEMM2 =================
        float C2[2][8][4];
        #pragma unroll
        for (int m = 0; m < 2; m++)
            #pragma unroll
            for (int n = 0; n < 8; n++)
                #pragma unroll
                for (int k = 0; k < 4; k++) C2[m][n][k] = 0.f;
        #pragma unroll
        for (int kt = 0; kt < 4; kt++) {
            #pragma unroll
            for (int nt2 = 0; nt2 < 4; nt2++) {
                uint32_t Bh[4], Bl[4];
                int br = nt2 * 16 + bRowL;
                uint32_t bd = smb + W2_HI + br * 128 + ((kt * 32 + bCbL) ^ ((br & 7) << 4));
                ldsm4(Bh, bd);
                ldsm4(Bl, bd + 8192);
                #pragma unroll
                for (int m = 0; m < 2; m++)
                    #pragma unroll
                    for (int p = 0; p < 2; p++) {
                        float* cc = C2[m][nt2 * 2 + p];
                        mma_bf16(cc, A2h[m][kt], Bh[2 * p], Bh[2 * p + 1]);
                        mma_bf16(cc, A2h[m][kt], Bl[2 * p], Bl[2 * p + 1]);
                        mma_bf16(cc, A2l[m][kt], Bh[2 * p], Bh[2 * p + 1]);
                    }
            }
        }

        // ---- epi2: feat = relu(C2 + be2); float4 atomics via pair exchange ----
        uint32_t A3h[2][4][4];
        #pragma unroll
        for (int m = 0; m < 2; m++) {
            int rr0 = __shfl_sync(FULLM, rI, m * 16 + qr);
            int rr1 = __shfl_sync(FULLM, rI, m * 16 + 8 + qr);
            #pragma unroll
            for (int nt = 0; nt < 8; nt++) {
                int col0 = nt * 8 + q2;
                float2 bb = *(float2*)(sMisc + 64 + col0);
                float f0 = fmaxf(C2[m][nt][0] + bb.x, 0.f);
                float f1 = fmaxf(C2[m][nt][1] + bb.y, 0.f);
                float f2 = fmaxf(C2[m][nt][2] + bb.x, 0.f);
                float f3 = fmaxf(C2[m][nt][3] + bb.y, 0.f);
                int kt = nt >> 1, o = (nt & 1) * 2;
                A3h[m][kt][o]     = packh(f0, f1);
                A3h[m][kt][o + 1] = packh(f2, f3);
                float g0 = __shfl_xor_sync(FULLM, f0, 1);
                float g1 = __shfl_xor_sync(FULLM, f1, 1);
                float g2 = __shfl_xor_sync(FULLM, f2, 1);
                float g3 = __shfl_xor_sync(FULLM, f3, 1);
                if ((lane & 1) == 0) {
                    int cb = nt * 8 + ((lane & 3) >> 1) * 4;
                    if (rr0 >= 0)
                        atomicAdd((float4*)(g_agg_h + (size_t)rr0 * 64 + cb),
                                  make_float4(f0, f1, g0, g1));
                    if (rr1 >= 0)
                        atomicAdd((float4*)(g_agg_h + (size_t)rr1 * 64 + cb),
                                  make_float4(f2, f3, g2, g3));
                }
            }
        }

        // ================= GEMM3 (gate, hi-only) =================
        float C3[2][8][4];
        #pragma unroll
        for (int m = 0; m < 2; m++)
            #pragma unroll
            for (int n = 0; n < 8; n++)
                #pragma unroll
                for (int k = 0; k < 4; k++) C3[m][n][k] = 0.f;
        #pragma unroll
        for (int kt = 0; kt < 4; kt++) {
            #pragma unroll
            for (int nt2 = 0; nt2 < 4; nt2++) {
                uint32_t Bh[4];
                int br = nt2 * 16 + bRowL;
                uint32_t bd = smb + WC_HI + br * 128 + ((kt * 32 + bCbL) ^ ((br & 7) << 4));
                ldsm4(Bh, bd);
                #pragma unroll
                for (int m = 0; m < 2; m++)
                    #pragma unroll
                    for (int p = 0; p < 2; p++)
                        mma_bf16(C3[m][nt2 * 2 + p], A3h[m][kt], Bh[2 * p], Bh[2 * p + 1]);
            }
        }

        // ---- epi3 ----
        #pragma unroll
        for (int m = 0; m < 2; m++) {
            float p0 = 0.f, p1 = 0.f;
            #pragma unroll
            for (int nt = 0; nt < 8; nt++) {
                int col0 = nt * 8 + q2;
                float2 bb = *(float2*)(sMisc + 128 + col0);
                float2 w2 = *(float2*)(sMisc + 192 + col0);
                p0 += fmaxf(C3[m][nt][0] + bb.x, 0.f) * w2.x
                    + fmaxf(C3[m][nt][1] + bb.y, 0.f) * w2.y;
                p1 += fmaxf(C3[m][nt][2] + bb.x, 0.f) * w2.x
                    + fmaxf(C3[m][nt][3] + bb.y, 0.f) * w2.y;
            }
            p0 += __shfl_xor_sync(FULLM, p0, 1);
            p0 += __shfl_xor_sync(FULLM, p0, 2);
            p1 += __shfl_xor_sync(FULLM, p1, 1);
            p1 += __shfl_xor_sync(FULLM, p1, 2);

            int row0 = m * 16 + qr, row1 = row0 + 8;
            float gx0 = __shfl_sync(FULLM, dx, row0), gy0 = __shfl_sync(FULLM, dy, row0),
                  gz0 = __shfl_sync(FULLM, dz, row0);
            float gx1 = __shfl_sync(FULLM, dx, row1), gy1 = __shfl_sync(FULLM, dy, row1),
                  gz1 = __shfl_sync(FULLM, dz, row1);
            int r0v = __shfl_sync(FULLM, rI, row0);
            int r1v = __shfl_sync(FULLM, rI, row1);

            if ((lane & 3) == 0) {
                if (r0v >= 0) {
                    float gt = p0 + bc2v;
                    atomicAdd(&g_sum4[r0v], make_float4(
                        fminf(fmaxf(gx0 * gt, -100.f), 100.f),
                        fminf(fmaxf(gy0 * gt, -100.f), 100.f),
                        fminf(fmaxf(gz0 * gt, -100.f), 100.f), 1.f));
                }
                if (r1v >= 0) {
                    float gt = p1 + bc2v;
                    atomicAdd(&g_sum4[r1v], make_float4(
                        fminf(fmaxf(gx1 * gt, -100.f), 100.f),
                        fminf(fmaxf(gy1 * gt, -100.f), 100.f),
                        fminf(fmaxf(gz1 * gt, -100.f), 100.f), 1.f));
                }
            }
        }
    }
}

// ===========================================================================
// Node kernel: bf16x3 HMMA, 320 threads / 10 warps; coord fused at head
// ===========================================================================
#define NTPB 320
#define NWARPS 10
#define NW1A 0
#define NW1B 16384
#define NW2  32768
#define NMISC 49152
#define NA_OFF 50176
#define SMEM_N (NA_OFF + NWARPS * 8192)

__global__ __launch_bounds__(NTPB, 1) void node_mma_kernel(
    const float* __restrict__ h,
    const float* __restrict__ Wn1, const float* __restrict__ bn1,
    const float* __restrict__ Wn2, const float* __restrict__ bn2,
    const float* __restrict__ coord, const float* __restrict__ vel,
    float* __restrict__ out_h, float* __restrict__ out_coord,
    float* __restrict__ out_v, int N)
{
    extern __shared__ char sm[];
    const uint32_t smb = smem_to_u32(sm);
    const int tid = threadIdx.x;
    float* sMisc = (float*)(sm + NMISC);

    for (int i = blockIdx.x * NTPB + tid; i < N; i += gridDim.x * NTPB) {
        float4 s = g_sum4[i];
        float c = s.w;
        float invc = (c > 0.f) ? (1.f / fmaxf(c, 1.f)) : 0.f;
        float vx = vel[i * 3 + 0] + s.x * invc * 0.125f;
        float vy = vel[i * 3 + 1] + s.y * invc * 0.125f;
        float vz = vel[i * 3 + 2] + s.z * invc * 0.125f;
        out_v[i * 3 + 0] = vx;
        out_v[i * 3 + 1] = vy;
        out_v[i * 3 + 2] = vz;
        out_coord[i * 3 + 0] = coord[i * 3 + 0] + vx * 0.125f;
        out_coord[i * 3 + 1] = coord[i * 3 + 1] + vy * 0.125f;
        out_coord[i * 3 + 2] = coord[i * 3 + 2] + vz * 0.125f;
    }

    for (int i = tid; i < 128 * 64; i += NTPB) {
        int k = i >> 6, j = i & 63;
        putw(sm, (k < 64) ? NW1A : NW1B, j, k & 63, Wn1[i]);
    }
    for (int i = tid; i < 64 * 64; i += NTPB) {
        int k = i >> 6, j = i & 63;
        putw(sm, NW2, j, k, Wn2[i]);
    }
    if (tid < 64)        sMisc[tid] = bn1[tid];
    else if (tid < 128)  sMisc[tid] = bn2[tid - 64];
    __syncthreads();

    const int warp = tid >> 5, lane = tid & 31;
    char* aPtr = sm + NA_OFF + warp * 8192;
    const uint32_t aHi = smb + NA_OFF + warp * 8192;

    const int aRowL = ((lane >> 3) & 1) * 8 + (lane & 7);
    const int aCbL  = ((lane >> 4) & 1) * 16;
    const int bRowL = ((lane >> 4) & 1) * 8 + (lane & 7);
    const int bCbL  = ((lane >> 3) & 1) * 16;
    const int q2 = (lane & 3) * 2;
    const int qr = lane >> 2;

    const int ntiles = (N + 31) >> 5;

    for (int t = blockIdx.x * NWARPS + warp; t < ntiles; t += gridDim.x * NWARPS) {
        const int nbase = t << 5;

        float C[2][8][4];
        #pragma unroll
        for (int m = 0; m < 2; m++)
            #pragma unroll
            for (int n = 0; n < 8; n++)
                #pragma unroll
                for (int k = 0; k < 4; k++) C[m][n][k] = 0.f;

        #pragma unroll
        for (int half = 0; half < 2; half++) {
            __syncwarp();
            const float* src = half ? g_agg_h : h;
            #pragma unroll
            for (int i = 0; i < 16; i++) {
                int row = (i << 1) | (lane >> 4);
                int node = nbase + row;
                if (node >= N) node = N - 1;
                float4 v = *(const float4*)(src + (size_t)node * 64 + (lane & 15) * 4);
                uint32_t h0, l0, h1, l1;
                packhl(v.x, v.y, h0, l0);
                packhl(v.z, v.w, h1, l1);
                uint32_t off = (uint32_t)(row * 128 + (((lane & 15) * 8) ^ ((row & 7) << 4)));
                *(uint2*)(aPtr + off)        = make_uint2(h0, h1);
                *(uint2*)(aPtr + 4096 + off) = make_uint2(l0, l1);
            }
            __syncwarp();

            const uint32_t wB = smb + (half ? NW1B : NW1A);
            #pragma unroll
            for (int kt = 0; kt < 4; kt++) {
                uint32_t Ah[2][4], Al[2][4];
                #pragma unroll
                for (int m = 0; m < 2; m++) {
                    int ar = m * 16 + aRowL;
                    uint32_t ad = aHi + ar * 128 + ((kt * 32 + aCbL) ^ ((ar & 7) << 4));
                    ldsm4(Ah[m], ad);
                    ldsm4(Al[m], ad + 4096);
                }
                #pragma unroll
                for (int nt2 = 0; nt2 < 4; nt2++) {
                    uint32_t Bh[4], Bl[4];
                    int br = nt2 * 16 + bRowL;
                    uint32_t bd = wB + br * 128 + ((kt * 32 + bCbL) ^ ((br & 7) << 4));
                    ldsm4(Bh, bd);
                    ldsm4(Bl, bd + 8192);
                    #pragma unroll
                    for (int m = 0; m < 2; m++)
                        #pragma unroll
                        for (int p = 0; p < 2; p++) {
                            float* cc = C[m][nt2 * 2 + p];
                            mma_bf16(cc, Ah[m], Bh[2 * p], Bh[2 * p + 1]);
                            mma_bf16(cc, Ah[m], Bl[2 * p], Bl[2 * p + 1]);
                            mma_bf16(cc, Al[m], Bh[2 * p], Bh[2 * p + 1]);
                        }
                }
            }
        }

        uint32_t A2h[2][4][4], A2l[2][4][4];
        #pragma unroll
        for (int m = 0; m < 2; m++) {
            #pragma unroll
            for (int nt = 0; nt < 8; nt++) {
                int col0 = nt * 8 + q2;
                float2 bb = *(float2*)(sMisc + col0);
                float c0 = fmaxf(C[m][nt][0] + bb.x, 0.f);
                float c1 = fmaxf(C[m][nt][1] + bb.y, 0.f);
                float c2 = fmaxf(C[m][nt][2] + bb.x, 0.f);
                float c3 = fmaxf(C[m][nt][3] + bb.y, 0.f);
                int kt = nt >> 1, o = (nt & 1) * 2;
                packhl(c0, c1, A2h[m][kt][o],     A2l[m][kt][o]);
                packhl(c2, c3, A2h[m][kt][o + 1], A2l[m][kt][o + 1]);
            }
        }

        float C2[2][8][4];
        #pragma unroll
        for (int m = 0; m < 2; m++)
            #pragma unroll
            for (int n = 0; n < 8; n++)
                #pragma unroll
                for (int k = 0; k < 4; k++) C2[m][n][k] = 0.f;
        #pragma unroll
        for (int kt = 0; kt < 4; kt++) {
            #pragma unroll
            for (int nt2 = 0; nt2 < 4; nt2++) {
                uint32_t Bh[4], Bl[4];
                int br = nt2 * 16 + bRowL;
                uint32_t bd = smb + NW2 + br * 128 + ((kt * 32 + bCbL) ^ ((br & 7) << 4));
                ldsm4(Bh, bd);
                ldsm4(Bl, bd + 8192);
                #pragma unroll
                for (int m = 0; m < 2; m++)
                    #pragma unroll
                    for (int p = 0; p < 2; p++) {
                        float* cc = C2[m][nt2 * 2 + p];
                        mma_bf16(cc, A2h[m][kt], Bh[2 * p], Bh[2 * p + 1]);
                        mma_bf16(cc, A2h[m][kt], Bl[2 * p], Bl[2 * p + 1]);
                        mma_bf16(cc, A2l[m][kt], Bh[2 * p], Bh[2 * p + 1]);
                    }
            }
        }

        #pragma unroll
        for (int m = 0; m < 2; m++) {
            int row0 = nbase + m * 16 + qr;
            int row1 = row0 + 8;
            bool v0 = row0 < N, v1 = row1 < N;
            #pragma unroll
            for (int nt = 0; nt < 8; nt++) {
                int col0 = nt * 8 + q2;
                float2 bb = *(float2*)(sMisc + 64 + col0);
                if (v0) {
                    float2 rs = *(const float2*)(h + (size_t)row0 * 64 + col0);
                    float2 o = make_float2(C2[m][nt][0] + bb.x + rs.x,
                                           C2[m][nt][1] + bb.y + rs.y);
                    *(float2*)(out_h + (size_t)row0 * 64 + col0) = o;
                }
                if (v1) {
                    float2 rs = *(const float2*)(h + (size_t)row1 * 64 + col0);
                    float2 o = make_float2(C2[m][nt][2] + bb.x + rs.x,
                                           C2[m][nt][3] + bb.y + rs.y);
                    *(float2*)(out_h + (size_t)row1 * 64 + col0) = o;
                }
            }
        }
    }
}

// ---------------------------------------------------------------------------
__global__ void zero_kernel(int n) {
    int total = n * 17;
    int stride = gridDim.x * blockDim.x;
    float4 z = make_float4(0.f, 0.f, 0.f, 0.f);
    for (int i = blockIdx.x * blockDim.x + threadIdx.x; i < total; i += stride) {
        if (i < n * 16) ((float4*)g_agg_h)[i] = z;
        else            g_sum4[i - n * 16] = z;
    }
}

// ---------------------------------------------------------------------------
extern "C" void kernel_launch(void* const* d_in, const int* in_sizes, int n_in,
                              void* d_out, int out_size)
{
    const float* h     = (const float*)d_in[0];
    const float* coord = (const float*)d_in[1];
    const float* vel   = (const float*)d_in[2];
    const int*   eidx  = (const int*)d_in[4];
    const float* We1 = (const float*)d_in[5];
    const float* be1 = (const float*)d_in[6];
    const float* We2 = (const float*)d_in[7];
    const float* be2 = (const float*)d_in[8];
    const float* Wn1 = (const float*)d_in[9];
    const float* bn1 = (const float*)d_in[10];
    const float* Wn2 = (const float*)d_in[11];
    const float* bn2 = (const float*)d_in[12];
    const float* Wc1 = (const float*)d_in[13];
    const float* bc1 = (const float*)d_in[14];
    const float* Wc2 = (const float*)d_in[15];
    const float* bc2 = (const float*)d_in[16];

    const int N = in_sizes[0] / 64;
    const int E = in_sizes[4] / 2;

    float* out       = (float*)d_out;
    float* out_h     = out;
    float* out_coord = out + (size_t)N * 64;
    float* out_v     = out_coord + (size_t)N * 3;

    cudaFuncSetAttribute(edge_mma_kernel, cudaFuncAttributeMaxDynamicSharedMemorySize, SMEM_E);
    cudaFuncSetAttribute(node_mma_kernel, cudaFuncAttributeMaxDynamicSharedMemorySize, SMEM_N);

    zero_kernel<<<512, 256>>>(N);
    edge_mma_kernel<<<148, ETPB, SMEM_E>>>(h, coord, eidx, E,
                                           We1, be1, We2, be2, Wc1, bc1, Wc2, bc2);
    node_mma_kernel<<<148, NTPB, SMEM_N>>>(h, Wn1, bn1, Wn2, bn2,
                                           coord, vel, out_h, out_coord, out_v, N);
}

// round 10
// speedup vs baseline: 1.5524x; 1.0217x over previous
#include <cuda_runtime.h>
#include <cuda_bf16.h>
#include <cstdint>

typedef unsigned long long u64;
#define FULLM 0xffffffffu

#define NMAX 50048
__device__ float  g_agg_h[(size_t)NMAX * 64];
__device__ float4 g_sum4[NMAX];
// prepacked weight images (byte-identical to kernel smem layouts)
#define PACKE_BYTES 58624   // W1A 16K | W1B 16K | W2 16K | WChi 8K | misc 1280
#define PACKN_BYTES 49664   // NW1A 16K | NW1B 16K | NW2 16K | misc 512
__device__ __align__(16) char g_packE[PACKE_BYTES];
__device__ __align__(16) char g_packN[PACKN_BYTES];

// ===========================================================================
// common helpers
// ===========================================================================
__device__ __forceinline__ uint32_t smem_to_u32(const void* p) {
    uint32_t a;
    asm("{ .reg .u64 t; cvta.to.shared.u64 t, %1; cvt.u32.u64 %0, t; }" : "=r"(a) : "l"(p));
    return a;
}
__device__ __forceinline__ void ldsm4(uint32_t r[4], uint32_t addr) {
    asm volatile("ldmatrix.sync.aligned.m8n8.x4.shared.b16 {%0,%1,%2,%3}, [%4];"
        : "=r"(r[0]), "=r"(r[1]), "=r"(r[2]), "=r"(r[3]) : "r"(addr));
}
__device__ __forceinline__ void mma_bf16(float c[4], const uint32_t a[4],
                                         uint32_t b0, uint32_t b1) {
    asm volatile("mma.sync.aligned.m16n8k16.row.col.f32.bf16.bf16.f32 "
        "{%0,%1,%2,%3},{%4,%5,%6,%7},{%8,%9},{%0,%1,%2,%3};"
        : "+f"(c[0]), "+f"(c[1]), "+f"(c[2]), "+f"(c[3])
        : "r"(a[0]), "r"(a[1]), "r"(a[2]), "r"(a[3]), "r"(b0), "r"(b1));
}
__device__ __forceinline__ void packhl(float a, float b, uint32_t &hi, uint32_t &lo) {
    __nv_bfloat162 hh = __floats2bfloat162_rn(a, b);
    float ra = a - __bfloat162float(hh.x);
    float rb = b - __bfloat162float(hh.y);
    __nv_bfloat162 ll = __floats2bfloat162_rn(ra, rb);
    hi = *(uint32_t*)&hh;
    lo = *(uint32_t*)&ll;
}
__device__ __forceinline__ uint32_t packh(float a, float b) {
    __nv_bfloat162 hh = __floats2bfloat162_rn(a, b);
    return *(uint32_t*)&hh;
}
__device__ __forceinline__ void putw(char* base, int plane, int j, int k, float x) {
    __nv_bfloat16 hb = __float2bfloat16(x);
    __nv_bfloat16 lb = __float2bfloat16(x - __bfloat162float(hb));
    uint32_t off = (uint32_t)(j * 128 + ((k * 2) ^ ((j & 7) << 4)));
    *(__nv_bfloat16*)(base + plane + off) = hb;
    *(__nv_bfloat16*)(base + plane + 8192 + off) = lb;
}
__device__ __forceinline__ void putw_hi(char* base, int plane, int j, int k, float x) {
    __nv_bfloat16 hb = __float2bfloat16(x);
    uint32_t off = (uint32_t)(j * 128 + ((k * 2) ^ ((j & 7) << 4)));
    *(__nv_bfloat16*)(base + plane + off) = hb;
}

// ===========================================================================
// Prep kernel: zero accumulators + pack weight images
// ===========================================================================
__global__ void prep_kernel(int n,
    const float* __restrict__ We1, const float* __restrict__ be1,
    const float* __restrict__ We2, const float* __restrict__ be2,
    const float* __restrict__ Wc1, const float* __restrict__ bc1,
    const float* __restrict__ Wc2,
    const float* __restrict__ Wn1, const float* __restrict__ bn1,
    const float* __restrict__ Wn2, const float* __restrict__ bn2)
{
    int gid = blockIdx.x * blockDim.x + threadIdx.x;
    int stride = gridDim.x * blockDim.x;
    float4 z = make_float4(0.f, 0.f, 0.f, 0.f);
    for (int i = gid; i < n * 17; i += stride) {
        if (i < n * 16) ((float4*)g_agg_h)[i] = z;
        else            g_sum4[i - n * 16] = z;
    }
    float* miscE = (float*)(g_packE + 57344);
    float* miscN = (float*)(g_packN + 49152);
    if (gid < 129 * 64) {
        int k = gid >> 6, j = gid & 63;
        float x = We1[gid];
        if (k < 128) putw(g_packE, (k < 64) ? 0 : 16384, j, k & 63, x);
        else         miscE[256 + j] = x;
    }
    if (gid < 64 * 64) {
        int k = gid >> 6, j = gid & 63;
        putw(g_packE, 32768, j, k, We2[gid]);
        putw_hi(g_packE, 49152, j, k, Wc1[gid]);
        putw(g_packN, 32768, j, k, Wn2[gid]);
    }
    if (gid < 128 * 64) {
        int k = gid >> 6, j = gid & 63;
        putw(g_packN, (k < 64) ? 0 : 16384, j, k & 63, Wn1[gid]);
    }
    if (gid < 64)        { miscE[gid] = be1[gid];            miscN[gid] = bn1[gid]; }
    else if (gid < 128)  { miscE[gid] = be2[gid - 64];       miscN[gid] = bn2[gid - 64]; }
    else if (gid < 192)  { miscE[gid] = bc1[gid - 128]; }
    else if (gid < 256)  { miscE[gid] = Wc2[gid - 192]; }
}

// ===========================================================================
// Edge kernel (R6 config: 320 thr / 10 warps, per-half gather)
// ===========================================================================
#define ETPB 320
#define EWARPS 10
#define W1A_HI   0
#define W1B_HI   16384
#define W2_HI    32768
#define WC_HI    49152
#define A_OFF    65536                       // per warp 8192 (hi|lo 4096)
#define MISC_OFF (A_OFF + EWARPS * 8192)
#define SMEM_E   (MISC_OFF + 1280)

__global__ __launch_bounds__(ETPB, 1) void edge_mma_kernel(
    const float* __restrict__ h, const float* __restrict__ coord,
    const int* __restrict__ eidx, int E, const float* __restrict__ bc2)
{
    extern __shared__ char sm[];
    const uint32_t smb = smem_to_u32(sm);
    const int tid = threadIdx.x;
    float* sMisc = (float*)(sm + MISC_OFF);

    // ---- stage weights: straight uint4 copy of pack image ----
    {
        const uint4* src = (const uint4*)g_packE;
        uint4* dst = (uint4*)sm;
        for (int i = tid; i < 3584; i += ETPB) dst[i] = src[i];   // 57344 B
        const uint4* ms = (const uint4*)(g_packE + 57344);
        uint4* md = (uint4*)(sm + MISC_OFF);
        if (tid < 80) md[tid] = ms[tid];                          // 1280 B
    }
    const float bc2v = bc2[0];
    __syncthreads();

    const int warp = tid >> 5, lane = tid & 31;
    char* aPtr = sm + A_OFF + warp * 8192;
    const uint32_t aHi = smb + A_OFF + warp * 8192;

    const int aRowL = ((lane >> 3) & 1) * 8 + (lane & 7);
    const int aCbL  = ((lane >> 4) & 1) * 16;
    const int bRowL = ((lane >> 4) & 1) * 8 + (lane & 7);
    const int bCbL  = ((lane >> 3) & 1) * 16;
    const int q2 = (lane & 3) * 2;
    const int qr = lane >> 2;

    const int estride = gridDim.x * ETPB;

    for (int e0 = (blockIdx.x * EWARPS + warp) * 32; e0 < E; e0 += estride) {
        int e = e0 + lane;
        bool valid = e < E;
        int ec = valid ? e : (E - 1);
        int r = eidx[ec], cI = eidx[E + ec];
        float dx = coord[r * 3 + 0] - coord[cI * 3 + 0];
        float dy = coord[r * 3 + 1] - coord[cI * 3 + 1];
        float dz = coord[r * 3 + 2] - coord[cI * 3 + 2];
        float rad = valid ? (dx * dx + dy * dy + dz * dz) : 0.f;
        int rI = valid ? r : -1;

        float C[2][8][4];
        #pragma unroll
        for (int m = 0; m < 2; m++)
            #pragma unroll
            for (int n = 0; n < 8; n++)
                #pragma unroll
                for (int k = 0; k < 4; k++) C[m][n][k] = 0.f;

        // ================= GEMM1 =================
        #pragma unroll
        for (int half = 0; half < 2; half++) {
            __syncwarp();
            #pragma unroll
            for (int i = 0; i < 16; i++) {
                int edge = (i << 1) | (lane >> 4);
                int node = __shfl_sync(FULLM, half ? cI : r, edge);
                float4 v = *(const float4*)(h + (size_t)node * 64 + (lane & 15) * 4);
                uint32_t h0, l0, h1, l1;
                packhl(v.x, v.y, h0, l0);
                packhl(v.z, v.w, h1, l1);
                uint32_t off = (uint32_t)(edge * 128 + (((lane & 15) * 8) ^ ((edge & 7) << 4)));
                *(uint2*)(aPtr + off)        = make_uint2(h0, h1);
                *(uint2*)(aPtr + 4096 + off) = make_uint2(l0, l1);
            }
            __syncwarp();

            const uint32_t wB = smb + (half ? W1B_HI : W1A_HI);
            #pragma unroll
            for (int kt = 0; kt < 4; kt++) {
                uint32_t Ah[2][4], Al[2][4];
                #pragma unroll
                for (int m = 0; m < 2; m++) {
                    int ar = m * 16 + aRowL;
                    uint32_t ad = aHi + ar * 128 + ((kt * 32 + aCbL) ^ ((ar & 7) << 4));
                    ldsm4(Ah[m], ad);
                    ldsm4(Al[m], ad + 4096);
                }
                #pragma unroll
                for (int nt2 = 0; nt2 < 4; nt2++) {
                    uint32_t Bh[4], Bl[4];
                    int br = nt2 * 16 + bRowL;
                    uint32_t bd = wB + br * 128 + ((kt * 32 + bCbL) ^ ((br & 7) << 4));
                    ldsm4(Bh, bd);
                    ldsm4(Bl, bd + 8192);
                    #pragma unroll
                    for (int m = 0; m < 2; m++)
                        #pragma unroll
                        for (int p = 0; p < 2; p++) {
                            float* cc = C[m][nt2 * 2 + p];
                            mma_bf16(cc, Ah[m], Bh[2 * p], Bh[2 * p + 1]);
                            mma_bf16(cc, Ah[m], Bl[2 * p], Bl[2 * p + 1]);
                            mma_bf16(cc, Al[m], Bh[2 * p], Bh[2 * p + 1]);
                        }
                }
            }
        }

        // ---- epi1 ----
        uint32_t A2h[2][4][4], A2l[2][4][4];
        #pragma unroll
        for (int m = 0; m < 2; m++) {
            float rad0 = __shfl_sync(FULLM, rad, m * 16 + qr);
            float rad1 = __shfl_sync(FULLM, rad, m * 16 + 8 + qr);
            #pragma unroll
            for (int nt = 0; nt < 8; nt++) {
                int col0 = nt * 8 + q2;
                float2 bb = *(float2*)(sMisc + col0);
                float2 wr = *(float2*)(sMisc + 256 + col0);
                float c0 = fmaxf(C[m][nt][0] + bb.x + rad0 * wr.x, 0.f);
                float c1 = fmaxf(C[m][nt][1] + bb.y + rad0 * wr.y, 0.f);
                float c2 = fmaxf(C[m][nt][2] + bb.x + rad1 * wr.x, 0.f);
                float c3 = fmaxf(C[m][nt][3] + bb.y + rad1 * wr.y, 0.f);
                int kt = nt >> 1, o = (nt & 1) * 2;
                packhl(c0, c1, A2h[m][kt][o],     A2l[m][kt][o]);
                packhl(c2, c3, A2h[m][kt][o + 1], A2l[m][kt][o + 1]);
            }
        }

        // ================= GEMM2 =================
        float C2[2][8][4];
        #pragma unroll
        for (int m = 0; m < 2; m++)
            #pragma unroll
            for (int n = 0; n < 8; n++)
                #pragma unroll
                for (int k = 0; k < 4; k++) C2[m][n][k] = 0.f;
        #pragma unroll
        for (int kt = 0; kt < 4; kt++) {
            #pragma unroll
            for (int nt2 = 0; nt2 < 4; nt2++) {
                uint32_t Bh[4], Bl[4];
                int br = nt2 * 16 + bRowL;
                uint32_t bd = smb + W2_HI + br * 128 + ((kt * 32 + bCbL) ^ ((br & 7) << 4));
                ldsm4(Bh, bd);
                ldsm4(Bl, bd + 8192);
                #pragma unroll
                for (int m = 0; m < 2; m++)
                    #pragma unroll
                    for (int p = 0; p < 2; p++) {
                        float* cc = C2[m][nt2 * 2 + p];
                        mma_bf16(cc, A2h[m][kt], Bh[2 * p], Bh[2 * p + 1]);
                        mma_bf16(cc, A2h[m][kt], Bl[2 * p], Bl[2 * p + 1]);
                        mma_bf16(cc, A2l[m][kt], Bh[2 * p], Bh[2 * p + 1]);
                    }
            }
        }

        // ---- epi2: feat = relu(C2 + be2); float4 atomics via pair exchange ----
        uint32_t A3h[2][4][4];
        #pragma unroll
        for (int m = 0; m < 2; m++) {
            int rr0 = __shfl_sync(FULLM, rI, m * 16 + qr);
            int rr1 = __shfl_sync(FULLM, rI, m * 16 + 8 + qr);
            #pragma unroll
            for (int nt = 0; nt < 8; nt++) {
                int col0 = nt * 8 + q2;
                float2 bb = *(float2*)(sMisc + 64 + col0);
                float f0 = fmaxf(C2[m][nt][0] + bb.x, 0.f);
                float f1 = fmaxf(C2[m][nt][1] + bb.y, 0.f);
                float f2 = fmaxf(C2[m][nt][2] + bb.x, 0.f);
                float f3 = fmaxf(C2[m][nt][3] + bb.y, 0.f);
                int kt = nt >> 1, o = (nt & 1) * 2;
                A3h[m][kt][o]     = packh(f0, f1);
                A3h[m][kt][o + 1] = packh(f2, f3);
                float g0 = __shfl_xor_sync(FULLM, f0, 1);
                float g1 = __shfl_xor_sync(FULLM, f1, 1);
                float g2 = __shfl_xor_sync(FULLM, f2, 1);
                float g3 = __shfl_xor_sync(FULLM, f3, 1);
                if ((lane & 1) == 0) {
                    int cb = nt * 8 + ((lane & 3) >> 1) * 4;
                    if (rr0 >= 0)
                        atomicAdd((float4*)(g_agg_h + (size_t)rr0 * 64 + cb),
                                  make_float4(f0, f1, g0, g1));
                    if (rr1 >= 0)
                        atomicAdd((float4*)(g_agg_h + (size_t)rr1 * 64 + cb),
                                  make_float4(f2, f3, g2, g3));
                }
            }
        }

        // ================= GEMM3 (gate, hi-only) =================
        float C3[2][8][4];
        #pragma unroll
        for (int m = 0; m < 2; m++)
            #pragma unroll
            for (int n = 0; n < 8; n++)
                #pragma unroll
                for (int k = 0; k < 4; k++) C3[m][n][k] = 0.f;
        #pragma unroll
        for (int kt = 0; kt < 4; kt++) {
            #pragma unroll
            for (int nt2 = 0; nt2 < 4; nt2++) {
                uint32_t Bh[4];
                int br = nt2 * 16 + bRowL;
                uint32_t bd = smb + WC_HI + br * 128 + ((kt * 32 + bCbL) ^ ((br & 7) << 4));
                ldsm4(Bh, bd);
                #pragma unroll
                for (int m = 0; m < 2; m++)
                    #pragma unroll
                    for (int p = 0; p < 2; p++)
                        mma_bf16(C3[m][nt2 * 2 + p], A3h[m][kt], Bh[2 * p], Bh[2 * p + 1]);
            }
        }

        // ---- epi3 ----
        #pragma unroll
        for (int m = 0; m < 2; m++) {
            float p0 = 0.f, p1 = 0.f;
            #pragma unroll
            for (int nt = 0; nt < 8; nt++) {
                int col0 = nt * 8 + q2;
                float2 bb = *(float2*)(sMisc + 128 + col0);
                float2 w2 = *(float2*)(sMisc + 192 + col0);
                p0 += fmaxf(C3[m][nt][0] + bb.x, 0.f) * w2.x
                    + fmaxf(C3[m][nt][1] + bb.y, 0.f) * w2.y;
                p1 += fmaxf(C3[m][nt][2] + bb.x, 0.f) * w2.x
                    + fmaxf(C3[m][nt][3] + bb.y, 0.f) * w2.y;
            }
            p0 += __shfl_xor_sync(FULLM, p0, 1);
            p0 += __shfl_xor_sync(FULLM, p0, 2);
            p1 += __shfl_xor_sync(FULLM, p1, 1);
            p1 += __shfl_xor_sync(FULLM, p1, 2);

            int row0 = m * 16 + qr, row1 = row0 + 8;
            float gx0 = __shfl_sync(FULLM, dx, row0), gy0 = __shfl_sync(FULLM, dy, row0),
                  gz0 = __shfl_sync(FULLM, dz, row0);
            float gx1 = __shfl_sync(FULLM, dx, row1), gy1 = __shfl_sync(FULLM, dy, row1),
                  gz1 = __shfl_sync(FULLM, dz, row1);
            int r0v = __shfl_sync(FULLM, rI, row0);
            int r1v = __shfl_sync(FULLM, rI, row1);

            if ((lane & 3) == 0) {
                if (r0v >= 0) {
                    float gt = p0 + bc2v;
                    atomicAdd(&g_sum4[r0v], make_float4(
                        fminf(fmaxf(gx0 * gt, -100.f), 100.f),
                        fminf(fmaxf(gy0 * gt, -100.f), 100.f),
                        fminf(fmaxf(gz0 * gt, -100.f), 100.f), 1.f));
                }
                if (r1v >= 0) {
                    float gt = p1 + bc2v;
                    atomicAdd(&g_sum4[r1v], make_float4(
                        fminf(fmaxf(gx1 * gt, -100.f), 100.f),
                        fminf(fmaxf(gy1 * gt, -100.f), 100.f),
                        fminf(fmaxf(gz1 * gt, -100.f), 100.f), 1.f));
                }
            }
        }
    }
}

// ===========================================================================
// Node kernel (R6 config: 256 thr / 8 warps; coord fused at head)
// ===========================================================================
#define NW2  32768
#define NMISC 49152
#define NA_OFF 50176
#define SMEM_N (NA_OFF + 8 * 8192)

__global__ __launch_bounds__(256, 1) void node_mma_kernel(
    const float* __restrict__ h,
    const float* __restrict__ coord, const float* __restrict__ vel,
    float* __restrict__ out_h, float* __restrict__ out_coord,
    float* __restrict__ out_v, int N)
{
    extern __shared__ char sm[];
    const uint32_t smb = smem_to_u32(sm);
    const int tid = threadIdx.x;
    float* sMisc = (float*)(sm + NMISC);

    // ---- fused coord/velocity update ----
    for (int i = blockIdx.x * 256 + tid; i < N; i += gridDim.x * 256) {
        float4 s = g_sum4[i];
        float c = s.w;
        float invc = (c > 0.f) ? (1.f / fmaxf(c, 1.f)) : 0.f;
        float vx = vel[i * 3 + 0] + s.x * invc * 0.125f;
        float vy = vel[i * 3 + 1] + s.y * invc * 0.125f;
        float vz = vel[i * 3 + 2] + s.z * invc * 0.125f;
        out_v[i * 3 + 0] = vx;
        out_v[i * 3 + 1] = vy;
        out_v[i * 3 + 2] = vz;
        out_coord[i * 3 + 0] = coord[i * 3 + 0] + vx * 0.125f;
        out_coord[i * 3 + 1] = coord[i * 3 + 1] + vy * 0.125f;
        out_coord[i * 3 + 2] = coord[i * 3 + 2] + vz * 0.125f;
    }

    // ---- stage weights: uint4 copy of pack image ----
    {
        const uint4* src = (const uint4*)g_packN;
        uint4* dst = (uint4*)sm;
        for (int i = tid; i < 3072; i += 256) dst[i] = src[i];    // 49152 B
        const uint4* ms = (const uint4*)(g_packN + 49152);
        uint4* md = (uint4*)(sm + NMISC);
        if (tid < 32) md[tid] = ms[tid];                          // 512 B
    }
    __syncthreads();

    const int warp = tid >> 5, lane = tid & 31;
    char* aPtr = sm + NA_OFF + warp * 8192;
    const uint32_t aHi = smb + NA_OFF + warp * 8192;

    const int aRowL = ((lane >> 3) & 1) * 8 + (lane & 7);
    const int aCbL  = ((lane >> 4) & 1) * 16;
    const int bRowL = ((lane >> 4) & 1) * 8 + (lane & 7);
    const int bCbL  = ((lane >> 3) & 1) * 16;
    const int q2 = (lane & 3) * 2;
    const int qr = lane >> 2;

    const int ntiles = (N + 31) >> 5;

    for (int t = blockIdx.x * 8 + warp; t < ntiles; t += gridDim.x * 8) {
        const int nbase = t << 5;

        float C[2][8][4];
        #pragma unroll
        for (int m = 0; m < 2; m++)
            #pragma unroll
            for (int n = 0; n < 8; n++)
                #pragma unroll
                for (int k = 0; k < 4; k++) C[m][n][k] = 0.f;

        #pragma unroll
        for (int half = 0; half < 2; half++) {
            __syncwarp();
            const float* src = half ? g_agg_h : h;
            #pragma unroll
            for (int i = 0; i < 16; i++) {
                int row = (i << 1) | (lane >> 4);
                int node = nbase + row;
                if (node >= N) node = N - 1;
                float4 v = *(const float4*)(src + (size_t)node * 64 + (lane & 15) * 4);
                uint32_t h0, l0, h1, l1;
                packhl(v.x, v.y, h0, l0);
                packhl(v.z, v.w, h1, l1);
                uint32_t off = (uint32_t)(row * 128 + (((lane & 15) * 8) ^ ((row & 7) << 4)));
                *(uint2*)(aPtr + off)        = make_uint2(h0, h1);
                *(uint2*)(aPtr + 4096 + off) = make_uint2(l0, l1);
            }
            __syncwarp();

            const uint32_t wB = smb + (half ? 16384 : 0);
            #pragma unroll
            for (int kt = 0; kt < 4; kt++) {
                uint32_t Ah[2][4], Al[2][4];
                #pragma unroll
                for (int m = 0; m < 2; m++) {
                    int ar = m * 16 + aRowL;
                    uint32_t ad = aHi + ar * 128 + ((kt * 32 + aCbL) ^ ((ar & 7) << 4));
                    ldsm4(Ah[m], ad);
                    ldsm4(Al[m], ad + 4096);
                }
                #pragma unroll
                for (int nt2 = 0; nt2 < 4; nt2++) {
                    uint32_t Bh[4], Bl[4];
                    int br = nt2 * 16 + bRowL;
                    uint32_t bd = wB + br * 128 + ((kt * 32 + bCbL) ^ ((br & 7) << 4));
                    ldsm4(Bh, bd);
                    ldsm4(Bl, bd + 8192);
                    #pragma unroll
                    for (int m = 0; m < 2; m++)
                        #pragma unroll
                        for (int p = 0; p < 2; p++) {
                            float* cc = C[m][nt2 * 2 + p];
                            mma_bf16(cc, Ah[m], Bh[2 * p], Bh[2 * p + 1]);
                            mma_bf16(cc, Ah[m], Bl[2 * p], Bl[2 * p + 1]);
                            mma_bf16(cc, Al[m], Bh[2 * p], Bh[2 * p + 1]);
                        }
                }
            }
        }

        uint32_t A2h[2][4][4], A2l[2][4][4];
        #pragma unroll
        for (int m = 0; m < 2; m++) {
            #pragma unroll
            for (int nt = 0; nt < 8; nt++) {
                int col0 = nt * 8 + q2;
                float2 bb = *(float2*)(sMisc + col0);
                float c0 = fmaxf(C[m][nt][0] + bb.x, 0.f);
                float c1 = fmaxf(C[m][nt][1] + bb.y, 0.f);
                float c2 = fmaxf(C[m][nt][2] + bb.x, 0.f);
                float c3 = fmaxf(C[m][nt][3] + bb.y, 0.f);
                int kt = nt >> 1, o = (nt & 1) * 2;
                packhl(c0, c1, A2h[m][kt][o],     A2l[m][kt][o]);
                packhl(c2, c3, A2h[m][kt][o + 1], A2l[m][kt][o + 1]);
            }
        }

        float C2[2][8][4];
        #pragma unroll
        for (int m = 0; m < 2; m++)
            #pragma unroll
            for (int n = 0; n < 8; n++)
                #pragma unroll
                for (int k = 0; k < 4; k++) C2[m][n][k] = 0.f;
        #pragma unroll
        for (int kt = 0; kt < 4; kt++) {
            #pragma unroll
            for (int nt2 = 0; nt2 < 4; nt2++) {
                uint32_t Bh[4], Bl[4];
                int br = nt2 * 16 + bRowL;
                uint32_t bd = smb + NW2 + br * 128 + ((kt * 32 + bCbL) ^ ((br & 7) << 4));
                ldsm4(Bh, bd);
                ldsm4(Bl, bd + 8192);
                #pragma unroll
                for (int m = 0; m < 2; m++)
                    #pragma unroll
                    for (int p = 0; p < 2; p++) {
                        float* cc = C2[m][nt2 * 2 + p];
                        mma_bf16(cc, A2h[m][kt], Bh[2 * p], Bh[2 * p + 1]);
                        mma_bf16(cc, A2h[m][kt], Bl[2 * p], Bl[2 * p + 1]);
                        mma_bf16(cc, A2l[m][kt], Bh[2 * p], Bh[2 * p + 1]);
                    }
            }
        }

        #pragma unroll
        for (int m = 0; m < 2; m++) {
            int row0 = nbase + m * 16 + qr;
            int row1 = row0 + 8;
            bool v0 = row0 < N, v1 = row1 < N;
            #pragma unroll
            for (int nt = 0; nt < 8; nt++) {
                int col0 = nt * 8 + q2;
                float2 bb = *(float2*)(sMisc + 64 + col0);
                if (v0) {
                    float2 rs = *(const float2*)(h + (size_t)row0 * 64 + col0);
                    float2 o = make_float2(C2[m][nt][0] + bb.x + rs.x,
                                           C2[m][nt][1] + bb.y + rs.y);
                    *(float2*)(out_h + (size_t)row0 * 64 + col0) = o;
                }
                if (v1) {
                    float2 rs = *(const float2*)(h + (size_t)row1 * 64 + col0);
                    float2 o = make_float2(C2[m][nt][2] + bb.x + rs.x,
                                           C2[m][nt][3] + bb.y + rs.y);
                    *(float2*)(out_h + (size_t)row1 * 64 + col0) = o;
                }
            }
        }
    }
}

// ---------------------------------------------------------------------------
extern "C" void kernel_launch(void* const* d_in, const int* in_sizes, int n_in,
                              void* d_out, int out_size)
{
    const float* h     = (const float*)d_in[0];
    const float* coord = (const float*)d_in[1];
    const float* vel   = (const float*)d_in[2];
    const int*   eidx  = (const int*)d_in[4];
    const float* We1 = (const float*)d_in[5];
    const float* be1 = (const float*)d_in[6];
    const float* We2 = (const float*)d_in[7];
    const float* be2 = (const float*)d_in[8];
    const float* Wn1 = (const float*)d_in[9];
    const float* bn1 = (const float*)d_in[10];
    const float* Wn2 = (const float*)d_in[11];
    const float* bn2 = (const float*)d_in[12];
    const float* Wc1 = (const float*)d_in[13];
    const float* bc1 = (const float*)d_in[14];
    const float* Wc2 = (const float*)d_in[15];
    const float* bc2 = (const float*)d_in[16];

    const int N = in_sizes[0] / 64;
    const int E = in_sizes[4] / 2;

    float* out       = (float*)d_out;
    float* out_h     = out;
    float* out_coord = out + (size_t)N * 64;
    float* out_v     = out_coord + (size_t)N * 3;

    cudaFuncSetAttribute(edge_mma_kernel, cudaFuncAttributeMaxDynamicSharedMemorySize, SMEM_E);
    cudaFuncSetAttribute(node_mma_kernel, cudaFuncAttributeMaxDynamicSharedMemorySize, SMEM_N);

    prep_kernel<<<512, 256>>>(N, We1, be1, We2, be2, Wc1, bc1, Wc2,
                              Wn1, bn1, Wn2, bn2);
    edge_mma_kernel<<<148, ETPB, SMEM_E>>>(h, coord, eidx, E, bc2);
    node_mma_kernel<<<148, 256, SMEM_N>>>(h, coord, vel,
                                          out_h, out_coord, out_v, N);
}

// round 11
// speedup vs baseline: 2.0541x; 1.3232x over previous
#include <cuda_runtime.h>
#include <cuda_bf16.h>
#include <cuda_fp16.h>
#include <cstdint>

typedef unsigned long long u64;
#define FULLM 0xffffffffu

#define NMAX 50048
__device__ float  g_agg_h[(size_t)NMAX * 64];
__device__ float4 g_sum4[NMAX];
// prepacked fp16 weight images (byte-identical to kernel smem layouts)
#define PACKE_BYTES 58624   // W1A hi/lo 16K | W1B 16K | W2 16K | WChi 8K | misc 1280
#define PACKN_BYTES 49664   // NW1A 16K | NW1B 16K | NW2 16K | misc 512
__device__ __align__(16) char g_packE[PACKE_BYTES];
__device__ __align__(16) char g_packN[PACKN_BYTES];

// ===========================================================================
// common helpers
// ===========================================================================
__device__ __forceinline__ uint32_t smem_to_u32(const void* p) {
    uint32_t a;
    asm("{ .reg .u64 t; cvta.to.shared.u64 t, %1; cvt.u32.u64 %0, t; }" : "=r"(a) : "l"(p));
    return a;
}
__device__ __forceinline__ void ldsm4(uint32_t r[4], uint32_t addr) {
    asm volatile("ldmatrix.sync.aligned.m8n8.x4.shared.b16 {%0,%1,%2,%3}, [%4];"
        : "=r"(r[0]), "=r"(r[1]), "=r"(r[2]), "=r"(r[3]) : "r"(addr));
}
__device__ __forceinline__ void mma_f16(float c[4], const uint32_t a[4],
                                        uint32_t b0, uint32_t b1) {
    asm volatile("mma.sync.aligned.m16n8k16.row.col.f32.f16.f16.f32 "
        "{%0,%1,%2,%3},{%4,%5,%6,%7},{%8,%9},{%0,%1,%2,%3};"
        : "+f"(c[0]), "+f"(c[1]), "+f"(c[2]), "+f"(c[3])
        : "r"(a[0]), "r"(a[1]), "r"(a[2]), "r"(a[3]), "r"(b0), "r"(b1));
}
__device__ __forceinline__ uint32_t pack2h(float a, float b) {
    __half2 hh = __floats2half2_rn(a, b);
    return *(uint32_t*)&hh;
}
__device__ __forceinline__ void putw16(char* base, int plane, int j, int k, float x) {
    __half hb = __float2half_rn(x);
    __half lb = __float2half_rn(x - __half2float(hb));
    uint32_t off = (uint32_t)(j * 128 + ((k * 2) ^ ((j & 7) << 4)));
    *(__half*)(base + plane + off) = hb;
    *(__half*)(base + plane + 8192 + off) = lb;
}
__device__ __forceinline__ void putw16_hi(char* base, int plane, int j, int k, float x) {
    __half hb = __float2half_rn(x);
    uint32_t off = (uint32_t)(j * 128 + ((k * 2) ^ ((j & 7) << 4)));
    *(__half*)(base + plane + off) = hb;
}

// ===========================================================================
// Prep kernel: zero accumulators + pack fp16 weight images
// ===========================================================================
__global__ void prep_kernel(int n,
    const float* __restrict__ We1, const float* __restrict__ be1,
    const float* __restrict__ We2, const float* __restrict__ be2,
    const float* __restrict__ Wc1, const float* __restrict__ bc1,
    const float* __restrict__ Wc2,
    const float* __restrict__ Wn1, const float* __restrict__ bn1,
    const float* __restrict__ Wn2, const float* __restrict__ bn2)
{
    int gid = blockIdx.x * blockDim.x + threadIdx.x;
    int stride = gridDim.x * blockDim.x;
    float4 z = make_float4(0.f, 0.f, 0.f, 0.f);
    for (int i = gid; i < n * 17; i += stride) {
        if (i < n * 16) ((float4*)g_agg_h)[i] = z;
        else            g_sum4[i - n * 16] = z;
    }
    float* miscE = (float*)(g_packE + 57344);
    float* miscN = (float*)(g_packN + 49152);
    if (gid < 129 * 64) {
        int k = gid >> 6, j = gid & 63;
        float x = We1[gid];
        if (k < 128) putw16(g_packE, (k < 64) ? 0 : 16384, j, k & 63, x);
        else         miscE[256 + j] = x;
    }
    if (gid < 64 * 64) {
        int k = gid >> 6, j = gid & 63;
        putw16(g_packE, 32768, j, k, We2[gid]);
        putw16_hi(g_packE, 49152, j, k, Wc1[gid]);
        putw16(g_packN, 32768, j, k, Wn2[gid]);
    }
    if (gid < 128 * 64) {
        int k = gid >> 6, j = gid & 63;
        putw16(g_packN, (k < 64) ? 0 : 16384, j, k & 63, Wn1[gid]);
    }
    if (gid < 64)        { miscE[gid] = be1[gid];            miscN[gid] = bn1[gid]; }
    else if (gid < 128)  { miscE[gid] = be2[gid - 64];       miscN[gid] = bn2[gid - 64]; }
    else if (gid < 192)  { miscE[gid] = bc1[gid - 128]; }
    else if (gid < 256)  { miscE[gid] = Wc2[gid - 192]; }
}

// ===========================================================================
// Edge kernel: fp16x2 HMMA, 320 thr / 10 warps, per-half gather (R6 structure)
// ===========================================================================
#define ETPB 320
#define EWARPS 10
#define W1A_HI   0
#define W1B_HI   16384
#define W2_HI    32768
#define WC_HI    49152
#define A_OFF    57344                       // per warp 4096 (hi only)
#define MISC_OFF (A_OFF + EWARPS * 4096)
#define SMEM_E   (MISC_OFF + 1280)

__global__ __launch_bounds__(ETPB, 1) void edge_mma_kernel(
    const float* __restrict__ h, const float* __restrict__ coord,
    const int* __restrict__ eidx, int E, const float* __restrict__ bc2)
{
    extern __shared__ char sm[];
    const uint32_t smb = smem_to_u32(sm);
    const int tid = threadIdx.x;
    float* sMisc = (float*)(sm + MISC_OFF);

    // ---- stage weights: straight uint4 copy of pack image ----
    {
        const uint4* src = (const uint4*)g_packE;
        uint4* dst = (uint4*)sm;
        for (int i = tid; i < 3584; i += ETPB) dst[i] = src[i];   // 57344 B
        const uint4* ms = (const uint4*)(g_packE + 57344);
        uint4* md = (uint4*)(sm + MISC_OFF);
        if (tid < 80) md[tid] = ms[tid];                          // 1280 B
    }
    const float bc2v = bc2[0];
    __syncthreads();

    const int warp = tid >> 5, lane = tid & 31;
    char* aPtr = sm + A_OFF + warp * 4096;
    const uint32_t aHi = smb + A_OFF + warp * 4096;

    const int aRowL = ((lane >> 3) & 1) * 8 + (lane & 7);
    const int aCbL  = ((lane >> 4) & 1) * 16;
    const int bRowL = ((lane >> 4) & 1) * 8 + (lane & 7);
    const int bCbL  = ((lane >> 3) & 1) * 16;
    const int q2 = (lane & 3) * 2;
    const int qr = lane >> 2;

    const int estride = gridDim.x * ETPB;

    for (int e0 = (blockIdx.x * EWARPS + warp) * 32; e0 < E; e0 += estride) {
        int e = e0 + lane;
        bool valid = e < E;
        int ec = valid ? e : (E - 1);
        int r = eidx[ec], cI = eidx[E + ec];
        float dx = coord[r * 3 + 0] - coord[cI * 3 + 0];
        float dy = coord[r * 3 + 1] - coord[cI * 3 + 1];
        float dz = coord[r * 3 + 2] - coord[cI * 3 + 2];
        float rad = valid ? (dx * dx + dy * dy + dz * dz) : 0.f;
        int rI = valid ? r : -1;

        float C[2][8][4];
        #pragma unroll
        for (int m = 0; m < 2; m++)
            #pragma unroll
            for (int n = 0; n < 8; n++)
                #pragma unroll
                for (int k = 0; k < 4; k++) C[m][n][k] = 0.f;

        // ================= GEMM1 =================
        #pragma unroll
        for (int half = 0; half < 2; half++) {
            __syncwarp();
            #pragma unroll
            for (int i = 0; i < 16; i++) {
                int edge = (i << 1) | (lane >> 4);
                int node = __shfl_sync(FULLM, half ? cI : r, edge);
                float4 v = *(const float4*)(h + (size_t)node * 64 + (lane & 15) * 4);
                uint32_t h0 = pack2h(v.x, v.y);
                uint32_t h1 = pack2h(v.z, v.w);
                uint32_t off = (uint32_t)(edge * 128 + (((lane & 15) * 8) ^ ((edge & 7) << 4)));
                *(uint2*)(aPtr + off) = make_uint2(h0, h1);
            }
            __syncwarp();

            const uint32_t wB = smb + (half ? W1B_HI : W1A_HI);
            #pragma unroll
            for (int kt = 0; kt < 4; kt++) {
                uint32_t Ah[2][4];
                #pragma unroll
                for (int m = 0; m < 2; m++) {
                    int ar = m * 16 + aRowL;
                    uint32_t ad = aHi + ar * 128 + ((kt * 32 + aCbL) ^ ((ar & 7) << 4));
                    ldsm4(Ah[m], ad);
                }
                #pragma unroll
                for (int nt2 = 0; nt2 < 4; nt2++) {
                    uint32_t Bh[4], Bl[4];
                    int br = nt2 * 16 + bRowL;
                    uint32_t bd = wB + br * 128 + ((kt * 32 + bCbL) ^ ((br & 7) << 4));
                    ldsm4(Bh, bd);
                    ldsm4(Bl, bd + 8192);
                    #pragma unroll
                    for (int m = 0; m < 2; m++)
                        #pragma unroll
                        for (int p = 0; p < 2; p++) {
                            float* cc = C[m][nt2 * 2 + p];
                            mma_f16(cc, Ah[m], Bh[2 * p], Bh[2 * p + 1]);
                            mma_f16(cc, Ah[m], Bl[2 * p], Bl[2 * p + 1]);
                        }
                }
            }
        }

        // ---- epi1: bias + radial (fp32), relu -> A2 fp16 frags ----
        uint32_t A2h[2][4][4];
        #pragma unroll
        for (int m = 0; m < 2; m++) {
            float rad0 = __shfl_sync(FULLM, rad, m * 16 + qr);
            float rad1 = __shfl_sync(FULLM, rad, m * 16 + 8 + qr);
            #pragma unroll
            for (int nt = 0; nt < 8; nt++) {
                int col0 = nt * 8 + q2;
                float2 bb = *(float2*)(sMisc + col0);
                float2 wr = *(float2*)(sMisc + 256 + col0);
                float c0 = fmaxf(C[m][nt][0] + bb.x + rad0 * wr.x, 0.f);
                float c1 = fmaxf(C[m][nt][1] + bb.y + rad0 * wr.y, 0.f);
                float c2 = fmaxf(C[m][nt][2] + bb.x + rad1 * wr.x, 0.f);
                float c3 = fmaxf(C[m][nt][3] + bb.y + rad1 * wr.y, 0.f);
                int kt = nt >> 1, o = (nt & 1) * 2;
                A2h[m][kt][o]     = pack2h(c0, c1);
                A2h[m][kt][o + 1] = pack2h(c2, c3);
            }
        }

        // ================= GEMM2 =================
        float C2[2][8][4];
        #pragma unroll
        for (int m = 0; m < 2; m++)
            #pragma unroll
            for (int n = 0; n < 8; n++)
                #pragma unroll
                for (int k = 0; k < 4; k++) C2[m][n][k] = 0.f;
        #pragma unroll
        for (int kt = 0; kt < 4; kt++) {
            #pragma unroll
            for (int nt2 = 0; nt2 < 4; nt2++) {
                uint32_t Bh[4], Bl[4];
                int br = nt2 * 16 + bRowL;
                uint32_t bd = smb + W2_HI + br * 128 + ((kt * 32 + bCbL) ^ ((br & 7) << 4));
                ldsm4(Bh, bd);
                ldsm4(Bl, bd + 8192);
                #pragma unroll
                for (int m = 0; m < 2; m++)
                    #pragma unroll
                    for (int p = 0; p < 2; p++) {
                        float* cc = C2[m][nt2 * 2 + p];
                        mma_f16(cc, A2h[m][kt], Bh[2 * p], Bh[2 * p + 1]);
                        mma_f16(cc, A2h[m][kt], Bl[2 * p], Bl[2 * p + 1]);
                    }
            }
        }

        // ---- epi2: feat = relu(C2 + be2) fp32; float4 atomics; A3 fp16 frags ----
        uint32_t A3h[2][4][4];
        #pragma unroll
        for (int m = 0; m < 2; m++) {
            int rr0 = __shfl_sync(FULLM, rI, m * 16 + qr);
            int rr1 = __shfl_sync(FULLM, rI, m * 16 + 8 + qr);
            #pragma unroll
            for (int nt = 0; nt < 8; nt++) {
                int col0 = nt * 8 + q2;
                float2 bb = *(float2*)(sMisc + 64 + col0);
                float f0 = fmaxf(C2[m][nt][0] + bb.x, 0.f);
                float f1 = fmaxf(C2[m][nt][1] + bb.y, 0.f);
                float f2 = fmaxf(C2[m][nt][2] + bb.x, 0.f);
                float f3 = fmaxf(C2[m][nt][3] + bb.y, 0.f);
                int kt = nt >> 1, o = (nt & 1) * 2;
                A3h[m][kt][o]     = pack2h(f0, f1);
                A3h[m][kt][o + 1] = pack2h(f2, f3);
                float g0 = __shfl_xor_sync(FULLM, f0, 1);
                float g1 = __shfl_xor_sync(FULLM, f1, 1);
                float g2 = __shfl_xor_sync(FULLM, f2, 1);
                float g3 = __shfl_xor_sync(FULLM, f3, 1);
                if ((lane & 1) == 0) {
                    int cb = nt * 8 + ((lane & 3) >> 1) * 4;
                    if (rr0 >= 0)
                        atomicAdd((float4*)(g_agg_h + (size_t)rr0 * 64 + cb),
                                  make_float4(f0, f1, g0, g1));
                    if (rr1 >= 0)
                        atomicAdd((float4*)(g_agg_h + (size_t)rr1 * 64 + cb),
                                  make_float4(f2, f3, g2, g3));
                }
            }
        }

        // ================= GEMM3 (gate, hi-only) =================
        float C3[2][8][4];
        #pragma unroll
        for (int m = 0; m < 2; m++)
            #pragma unroll
            for (int n = 0; n < 8; n++)
                #pragma unroll
                for (int k = 0; k < 4; k++) C3[m][n][k] = 0.f;
        #pragma unroll
        for (int kt = 0; kt < 4; kt++) {
            #pragma unroll
            for (int nt2 = 0; nt2 < 4; nt2++) {
                uint32_t Bh[4];
                int br = nt2 * 16 + bRowL;
                uint32_t bd = smb + WC_HI + br * 128 + ((kt * 32 + bCbL) ^ ((br & 7) << 4));
                ldsm4(Bh, bd);
                #pragma unroll
                for (int m = 0; m < 2; m++)
                    #pragma unroll
                    for (int p = 0; p < 2; p++)
                        mma_f16(C3[m][nt2 * 2 + p], A3h[m][kt], Bh[2 * p], Bh[2 * p + 1]);
            }
        }

        // ---- epi3 ----
        #pragma unroll
        for (int m = 0; m < 2; m++) {
            float p0 = 0.f, p1 = 0.f;
            #pragma unroll
            for (int nt = 0; nt < 8; nt++) {
                int col0 = nt * 8 + q2;
                float2 bb = *(float2*)(sMisc + 128 + col0);
                float2 w2 = *(float2*)(sMisc + 192 + col0);
                p0 += fmaxf(C3[m][nt][0] + bb.x, 0.f) * w2.x
                    + fmaxf(C3[m][nt][1] + bb.y, 0.f) * w2.y;
                p1 += fmaxf(C3[m][nt][2] + bb.x, 0.f) * w2.x
                    + fmaxf(C3[m][nt][3] + bb.y, 0.f) * w2.y;
            }
            p0 += __shfl_xor_sync(FULLM, p0, 1);
            p0 += __shfl_xor_sync(FULLM, p0, 2);
            p1 += __shfl_xor_sync(FULLM, p1, 1);
            p1 += __shfl_xor_sync(FULLM, p1, 2);

            int row0 = m * 16 + qr, row1 = row0 + 8;
            float gx0 = __shfl_sync(FULLM, dx, row0), gy0 = __shfl_sync(FULLM, dy, row0),
                  gz0 = __shfl_sync(FULLM, dz, row0);
            float gx1 = __shfl_sync(FULLM, dx, row1), gy1 = __shfl_sync(FULLM, dy, row1),
                  gz1 = __shfl_sync(FULLM, dz, row1);
            int r0v = __shfl_sync(FULLM, rI, row0);
            int r1v = __shfl_sync(FULLM, rI, row1);

            if ((lane & 3) == 0) {
                if (r0v >= 0) {
                    float gt = p0 + bc2v;
                    atomicAdd(&g_sum4[r0v], make_float4(
                        fminf(fmaxf(gx0 * gt, -100.f), 100.f),
                        fminf(fmaxf(gy0 * gt, -100.f), 100.f),
                        fminf(fmaxf(gz0 * gt, -100.f), 100.f), 1.f));
                }
                if (r1v >= 0) {
                    float gt = p1 + bc2v;
                    atomicAdd(&g_sum4[r1v], make_float4(
                        fminf(fmaxf(gx1 * gt, -100.f), 100.f),
                        fminf(fmaxf(gy1 * gt, -100.f), 100.f),
                        fminf(fmaxf(gz1 * gt, -100.f), 100.f), 1.f));
                }
            }
        }
    }
}

// ===========================================================================
// Node kernel: fp16x2 HMMA, 256 thr / 8 warps; coord fused at head
// ===========================================================================
#define NW2  32768
#define NMISC 49152
#define NA_OFF 49664
#define SMEM_N (NA_OFF + 8 * 4096)

__global__ __launch_bounds__(256, 1) void node_mma_kernel(
    const float* __restrict__ h,
    const float* __restrict__ coord, const float* __restrict__ vel,
    float* __restrict__ out_h, float* __restrict__ out_coord,
    float* __restrict__ out_v, int N)
{
    extern __shared__ char sm[];
    const uint32_t smb = smem_to_u32(sm);
    const int tid = threadIdx.x;
    float* sMisc = (float*)(sm + NMISC);

    for (int i = blockIdx.x * 256 + tid; i < N; i += gridDim.x * 256) {
        float4 s = g_sum4[i];
        float c = s.w;
        float invc = (c > 0.f) ? (1.f / fmaxf(c, 1.f)) : 0.f;
        float vx = vel[i * 3 + 0] + s.x * invc * 0.125f;
        float vy = vel[i * 3 + 1] + s.y * invc * 0.125f;
        float vz = vel[i * 3 + 2] + s.z * invc * 0.125f;
        out_v[i * 3 + 0] = vx;
        out_v[i * 3 + 1] = vy;
        out_v[i * 3 + 2] = vz;
        out_coord[i * 3 + 0] = coord[i * 3 + 0] + vx * 0.125f;
        out_coord[i * 3 + 1] = coord[i * 3 + 1] + vy * 0.125f;
        out_coord[i * 3 + 2] = coord[i * 3 + 2] + vz * 0.125f;
    }

    {
        const uint4* src = (const uint4*)g_packN;
        uint4* dst = (uint4*)sm;
        for (int i = tid; i < 3072; i += 256) dst[i] = src[i];    // 49152 B
        const uint4* ms = (const uint4*)(g_packN + 49152);
        uint4* md = (uint4*)(sm + NMISC);
        if (tid < 32) md[tid] = ms[tid];                          // 512 B
    }
    __syncthreads();

    const int warp = tid >> 5, lane = tid & 31;
    char* aPtr = sm + NA_OFF + warp * 4096;
    const uint32_t aHi = smb + NA_OFF + warp * 4096;

    const int aRowL = ((lane >> 3) & 1) * 8 + (lane & 7);
    const int aCbL  = ((lane >> 4) & 1) * 16;
    const int bRowL = ((lane >> 4) & 1) * 8 + (lane & 7);
    const int bCbL  = ((lane >> 3) & 1) * 16;
    const int q2 = (lane & 3) * 2;
    const int qr = lane >> 2;

    const int ntiles = (N + 31) >> 5;

    for (int t = blockIdx.x * 8 + warp; t < ntiles; t += gridDim.x * 8) {
        const int nbase = t << 5;

        float C[2][8][4];
        #pragma unroll
        for (int m = 0; m < 2; m++)
            #pragma unroll
            for (int n = 0; n < 8; n++)
                #pragma unroll
                for (int k = 0; k < 4; k++) C[m][n][k] = 0.f;

        #pragma unroll
        for (int half = 0; half < 2; half++) {
            __syncwarp();
            const float* src = half ? g_agg_h : h;
            #pragma unroll
            for (int i = 0; i < 16; i++) {
                int row = (i << 1) | (lane >> 4);
                int node = nbase + row;
                if (node >= N) node = N - 1;
                float4 v = *(const float4*)(src + (size_t)node * 64 + (lane & 15) * 4);
                uint32_t h0 = pack2h(v.x, v.y);
                uint32_t h1 = pack2h(v.z, v.w);
                uint32_t off = (uint32_t)(row * 128 + (((lane & 15) * 8) ^ ((row & 7) << 4)));
                *(uint2*)(aPtr + off) = make_uint2(h0, h1);
            }
            __syncwarp();

            const uint32_t wB = smb + (half ? 16384 : 0);
            #pragma unroll
            for (int kt = 0; kt < 4; kt++) {
                uint32_t Ah[2][4];
                #pragma unroll
                for (int m = 0; m < 2; m++) {
                    int ar = m * 16 + aRowL;
                    uint32_t ad = aHi + ar * 128 + ((kt * 32 + aCbL) ^ ((ar & 7) << 4));
                    ldsm4(Ah[m], ad);
                }
                #pragma unroll
                for (int nt2 = 0; nt2 < 4; nt2++) {
                    uint32_t Bh[4], Bl[4];
                    int br = nt2 * 16 + bRowL;
                    uint32_t bd = wB + br * 128 + ((kt * 32 + bCbL) ^ ((br & 7) << 4));
                    ldsm4(Bh, bd);
                    ldsm4(Bl, bd + 8192);
                    #pragma unroll
                    for (int m = 0; m < 2; m++)
                        #pragma unroll
                        for (int p = 0; p < 2; p++) {
                            float* cc = C[m][nt2 * 2 + p];
                            mma_f16(cc, Ah[m], Bh[2 * p], Bh[2 * p + 1]);
                            mma_f16(cc, Ah[m], Bl[2 * p], Bl[2 * p + 1]);
                        }
                }
            }
        }

        uint32_t A2h[2][4][4];
        #pragma unroll
        for (int m = 0; m < 2; m++) {
            #pragma unroll
            for (int nt = 0; nt < 8; nt++) {
                int col0 = nt * 8 + q2;
                float2 bb = *(float2*)(sMisc + col0);
                float c0 = fmaxf(C[m][nt][0] + bb.x, 0.f);
                float c1 = fmaxf(C[m][nt][1] + bb.y, 0.f);
                float c2 = fmaxf(C[m][nt][2] + bb.x, 0.f);
                float c3 = fmaxf(C[m][nt][3] + bb.y, 0.f);
                int kt = nt >> 1, o = (nt & 1) * 2;
                A2h[m][kt][o]     = pack2h(c0, c1);
                A2h[m][kt][o + 1] = pack2h(c2, c3);
            }
        }

        float C2[2][8][4];
        #pragma unroll
        for (int m = 0; m < 2; m++)
            #pragma unroll
            for (int n = 0; n < 8; n++)
                #pragma unroll
                for (int k = 0; k < 4; k++) C2[m][n][k] = 0.f;
        #pragma unroll
        for (int kt = 0; kt < 4; kt++) {
            #pragma unroll
            for (int nt2 = 0; nt2 < 4; nt2++) {
                uint32_t Bh[4], Bl[4];
                int br = nt2 * 16 + bRowL;
                uint32_t bd = smb + NW2 + br * 128 + ((kt * 32 + bCbL) ^ ((br & 7) << 4));
                ldsm4(Bh, bd);
                ldsm4(Bl, bd + 8192);
                #pragma unroll
                for (int m = 0; m < 2; m++)
                    #pragma unroll
                    for (int p = 0; p < 2; p++) {
                        float* cc = C2[m][nt2 * 2 + p];
                        mma_f16(cc, A2h[m][kt], Bh[2 * p], Bh[2 * p + 1]);
                        mma_f16(cc, A2h[m][kt], Bl[2 * p], Bl[2 * p + 1]);
                    }
            }
        }

        #pragma unroll
        for (int m = 0; m < 2; m++) {
            int row0 = nbase + m * 16 + qr;
            int row1 = row0 + 8;
            bool v0 = row0 < N, v1 = row1 < N;
            #pragma unroll
            for (int nt = 0; nt < 8; nt++) {
                int col0 = nt * 8 + q2;
                float2 bb = *(float2*)(sMisc + 64 + col0);
                if (v0) {
                    float2 rs = *(const float2*)(h + (size_t)row0 * 64 + col0);
                    float2 o = make_float2(C2[m][nt][0] + bb.x + rs.x,
                                           C2[m][nt][1] + bb.y + rs.y);
                    *(float2*)(out_h + (size_t)row0 * 64 + col0) = o;
                }
                if (v1) {
                    float2 rs = *(const float2*)(h + (size_t)row1 * 64 + col0);
                    float2 o = make_float2(C2[m][nt][2] + bb.x + rs.x,
                                           C2[m][nt][3] + bb.y + rs.y);
                    *(float2*)(out_h + (size_t)row1 * 64 + col0) = o;
                }
            }
        }
    }
}

// ---------------------------------------------------------------------------
extern "C" void kernel_launch(void* const* d_in, const int* in_sizes, int n_in,
                              void* d_out, int out_size)
{
    const float* h     = (const float*)d_in[0];
    const float* coord = (const float*)d_in[1];
    const float* vel   = (const float*)d_in[2];
    const int*   eidx  = (const int*)d_in[4];
    const float* We1 = (const float*)d_in[5];
    const float* be1 = (const float*)d_in[6];
    const float* We2 = (const float*)d_in[7];
    const float* be2 = (const float*)d_in[8];
    const float* Wn1 = (const float*)d_in[9];
    const float* bn1 = (const float*)d_in[10];
    const float* Wn2 = (const float*)d_in[11];
    const float* bn2 = (const float*)d_in[12];
    const float* Wc1 = (const float*)d_in[13];
    const float* bc1 = (const float*)d_in[14];
    const float* Wc2 = (const float*)d_in[15];
    const float* bc2 = (const float*)d_in[16];

    const int N = in_sizes[0] / 64;
    const int E = in_sizes[4] / 2;

    float* out       = (float*)d_out;
    float* out_h     = out;
    float* out_coord = out + (size_t)N * 64;
    float* out_v     = out_coord + (size_t)N * 3;

    cudaFuncSetAttribute(edge_mma_kernel, cudaFuncAttributeMaxDynamicSharedMemorySize, SMEM_E);
    cudaFuncSetAttribute(node_mma_kernel, cudaFuncAttributeMaxDynamicSharedMemorySize, SMEM_N);

    prep_kernel<<<512, 256>>>(N, We1, be1, We2, be2, Wc1, bc1, Wc2,
                              Wn1, bn1, Wn2, bn2);
    edge_mma_kernel<<<148, ETPB, SMEM_E>>>(h, coord, eidx, E, bc2);
    node_mma_kernel<<<148, 256, SMEM_N>>>(h, coord, vel,
                                          out_h, out_coord, out_v, N);
}

// round 12
// speedup vs baseline: 2.5618x; 1.2471x over previous
#include <cuda_runtime.h>
#include <cuda_fp16.h>
#include <cstdint>

typedef unsigned long long u64;
#define FULLM 0xffffffffu

#define NMAX 50048
__device__ float  g_agg_h[(size_t)NMAX * 64];
__device__ float4 g_sum4[NMAX];
// prepacked fp16 weight images (byte-identical to kernel smem layouts)
#define PACKE_BYTES 34048   // W1A 8K | W1B 8K | W2 8K | WC 8K | misc 1280
#define PACKN_BYTES 25088   // NW1A 8K | NW1B 8K | NW2 8K | misc 512
__device__ __align__(16) char g_packE[PACKE_BYTES];
__device__ __align__(16) char g_packN[PACKN_BYTES];

// ===========================================================================
// common helpers
// ===========================================================================
__device__ __forceinline__ uint32_t smem_to_u32(const void* p) {
    uint32_t a;
    asm("{ .reg .u64 t; cvta.to.shared.u64 t, %1; cvt.u32.u64 %0, t; }" : "=r"(a) : "l"(p));
    return a;
}
__device__ __forceinline__ void ldsm4(uint32_t r[4], uint32_t addr) {
    asm volatile("ldmatrix.sync.aligned.m8n8.x4.shared.b16 {%0,%1,%2,%3}, [%4];"
        : "=r"(r[0]), "=r"(r[1]), "=r"(r[2]), "=r"(r[3]) : "r"(addr));
}
__device__ __forceinline__ void mma_f16(float c[4], const uint32_t a[4],
                                        uint32_t b0, uint32_t b1) {
    asm volatile("mma.sync.aligned.m16n8k16.row.col.f32.f16.f16.f32 "
        "{%0,%1,%2,%3},{%4,%5,%6,%7},{%8,%9},{%0,%1,%2,%3};"
        : "+f"(c[0]), "+f"(c[1]), "+f"(c[2]), "+f"(c[3])
        : "r"(a[0]), "r"(a[1]), "r"(a[2]), "r"(a[3]), "r"(b0), "r"(b1));
}
__device__ __forceinline__ uint32_t pack2h(float a, float b) {
    __half2 hh = __floats2half2_rn(a, b);
    return *(uint32_t*)&hh;
}
__device__ __forceinline__ void putw16(char* base, int plane, int j, int k, float x) {
    __half hb = __float2half_rn(x);
    uint32_t off = (uint32_t)(j * 128 + ((k * 2) ^ ((j & 7) << 4)));
    *(__half*)(base + plane + off) = hb;
}

// ===========================================================================
// Prep kernel: zero accumulators + pack fp16 weight images
// ===========================================================================
__global__ void prep_kernel(int n,
    const float* __restrict__ We1, const float* __restrict__ be1,
    const float* __restrict__ We2, const float* __restrict__ be2,
    const float* __restrict__ Wc1, const float* __restrict__ bc1,
    const float* __restrict__ Wc2,
    const float* __restrict__ Wn1, const float* __restrict__ bn1,
    const float* __restrict__ Wn2, const float* __restrict__ bn2)
{
    int gid = blockIdx.x * blockDim.x + threadIdx.x;
    int stride = gridDim.x * blockDim.x;
    float4 z = make_float4(0.f, 0.f, 0.f, 0.f);
    for (int i = gid; i < n * 17; i += stride) {
        if (i < n * 16) ((float4*)g_agg_h)[i] = z;
        else            g_sum4[i - n * 16] = z;
    }
    float* miscE = (float*)(g_packE + 32768);
    float* miscN = (float*)(g_packN + 24576);
    if (gid < 129 * 64) {
        int k = gid >> 6, j = gid & 63;
        float x = We1[gid];
        if (k < 128) putw16(g_packE, (k < 64) ? 0 : 8192, j, k & 63, x);
        else         miscE[256 + j] = x;
    }
    if (gid < 64 * 64) {
        int k = gid >> 6, j = gid & 63;
        putw16(g_packE, 16384, j, k, We2[gid]);
        putw16(g_packE, 24576, j, k, Wc1[gid]);
        putw16(g_packN, 16384, j, k, Wn2[gid]);
    }
    if (gid < 128 * 64) {
        int k = gid >> 6, j = gid & 63;
        putw16(g_packN, (k < 64) ? 0 : 8192, j, k & 63, Wn1[gid]);
    }
    if (gid < 64)        { miscE[gid] = be1[gid];            miscN[gid] = bn1[gid]; }
    else if (gid < 128)  { miscE[gid] = be2[gid - 64];       miscN[gid] = bn2[gid - 64]; }
    else if (gid < 192)  { miscE[gid] = bc1[gid - 128]; }
    else if (gid < 256)  { miscE[gid] = Wc2[gid - 192]; }
}

// ===========================================================================
// Edge kernel: pure fp16 HMMA, 320 thr / 10 warps, per-half gather
// ===========================================================================
#define ETPB 320
#define EWARPS 10
#define W1A_HI   0
#define W1B_HI   8192
#define W2_HI    16384
#define WC_HI    24576
#define A_OFF    32768                       // per warp 4096
#define MISC_OFF (A_OFF + EWARPS * 4096)     // 73728
#define SMEM_E   (MISC_OFF + 1280)

__global__ __launch_bounds__(ETPB, 1) void edge_mma_kernel(
    const float* __restrict__ h, const float* __restrict__ coord,
    const int* __restrict__ eidx, int E, const float* __restrict__ bc2)
{
    extern __shared__ char sm[];
    const uint32_t smb = smem_to_u32(sm);
    const int tid = threadIdx.x;
    float* sMisc = (float*)(sm + MISC_OFF);

    // ---- stage weights: straight uint4 copy of pack image ----
    {
        const uint4* src = (const uint4*)g_packE;
        uint4* dst = (uint4*)sm;
        for (int i = tid; i < 2048; i += ETPB) dst[i] = src[i];   // 32768 B
        const uint4* ms = (const uint4*)(g_packE + 32768);
        uint4* md = (uint4*)(sm + MISC_OFF);
        if (tid < 80) md[tid] = ms[tid];                          // 1280 B
    }
    const float bc2v = bc2[0];
    __syncthreads();

    const int warp = tid >> 5, lane = tid & 31;
    char* aPtr = sm + A_OFF + warp * 4096;
    const uint32_t aHi = smb + A_OFF + warp * 4096;

    const int aRowL = ((lane >> 3) & 1) * 8 + (lane & 7);
    const int aCbL  = ((lane >> 4) & 1) * 16;
    const int bRowL = ((lane >> 4) & 1) * 8 + (lane & 7);
    const int bCbL  = ((lane >> 3) & 1) * 16;
    const int q2 = (lane & 3) * 2;
    const int qr = lane >> 2;

    const int estride = gridDim.x * ETPB;

    for (int e0 = (blockIdx.x * EWARPS + warp) * 32; e0 < E; e0 += estride) {
        int e = e0 + lane;
        bool valid = e < E;
        int ec = valid ? e : (E - 1);
        int r = eidx[ec], cI = eidx[E + ec];
        float dx = coord[r * 3 + 0] - coord[cI * 3 + 0];
        float dy = coord[r * 3 + 1] - coord[cI * 3 + 1];
        float dz = coord[r * 3 + 2] - coord[cI * 3 + 2];
        float rad = valid ? (dx * dx + dy * dy + dz * dz) : 0.f;
        int rI = valid ? r : -1;

        float C[2][8][4];
        #pragma unroll
        for (int m = 0; m < 2; m++)
            #pragma unroll
            for (int n = 0; n < 8; n++)
                #pragma unroll
                for (int k = 0; k < 4; k++) C[m][n][k] = 0.f;

        // ================= GEMM1 =================
        #pragma unroll
        for (int half = 0; half < 2; half++) {
            __syncwarp();
            #pragma unroll
            for (int i = 0; i < 16; i++) {
                int edge = (i << 1) | (lane >> 4);
                int node = __shfl_sync(FULLM, half ? cI : r, edge);
                float4 v = *(const float4*)(h + (size_t)node * 64 + (lane & 15) * 4);
                uint32_t h0 = pack2h(v.x, v.y);
                uint32_t h1 = pack2h(v.z, v.w);
                uint32_t off = (uint32_t)(edge * 128 + (((lane & 15) * 8) ^ ((edge & 7) << 4)));
                *(uint2*)(aPtr + off) = make_uint2(h0, h1);
            }
            __syncwarp();

            const uint32_t wB = smb + (half ? W1B_HI : W1A_HI);
            #pragma unroll
            for (int kt = 0; kt < 4; kt++) {
                uint32_t Ah[2][4];
                #pragma unroll
                for (int m = 0; m < 2; m++) {
                    int ar = m * 16 + aRowL;
                    uint32_t ad = aHi + ar * 128 + ((kt * 32 + aCbL) ^ ((ar & 7) << 4));
                    ldsm4(Ah[m], ad);
                }
                #pragma unroll
                for (int nt2 = 0; nt2 < 4; nt2++) {
                    uint32_t Bh[4];
                    int br = nt2 * 16 + bRowL;
                    uint32_t bd = wB + br * 128 + ((kt * 32 + bCbL) ^ ((br & 7) << 4));
                    ldsm4(Bh, bd);
                    #pragma unroll
                    for (int m = 0; m < 2; m++)
                        #pragma unroll
                        for (int p = 0; p < 2; p++)
                            mma_f16(C[m][nt2 * 2 + p], Ah[m], Bh[2 * p], Bh[2 * p + 1]);
                }
            }
        }

        // ---- epi1: bias + radial (fp32), relu -> A2 fp16 frags ----
        uint32_t A2h[2][4][4];
        #pragma unroll
        for (int m = 0; m < 2; m++) {
            float rad0 = __shfl_sync(FULLM, rad, m * 16 + qr);
            float rad1 = __shfl_sync(FULLM, rad, m * 16 + 8 + qr);
            #pragma unroll
            for (int nt = 0; nt < 8; nt++) {
                int col0 = nt * 8 + q2;
                float2 bb = *(float2*)(sMisc + col0);
                float2 wr = *(float2*)(sMisc + 256 + col0);
                float c0 = fmaxf(C[m][nt][0] + bb.x + rad0 * wr.x, 0.f);
                float c1 = fmaxf(C[m][nt][1] + bb.y + rad0 * wr.y, 0.f);
                float c2 = fmaxf(C[m][nt][2] + bb.x + rad1 * wr.x, 0.f);
                float c3 = fmaxf(C[m][nt][3] + bb.y + rad1 * wr.y, 0.f);
                int kt = nt >> 1, o = (nt & 1) * 2;
                A2h[m][kt][o]     = pack2h(c0, c1);
                A2h[m][kt][o + 1] = pack2h(c2, c3);
            }
        }

        // ================= GEMM2 =================
        float C2[2][8][4];
        #pragma unroll
        for (int m = 0; m < 2; m++)
            #pragma unroll
            for (int n = 0; n < 8; n++)
                #pragma unroll
                for (int k = 0; k < 4; k++) C2[m][n][k] = 0.f;
        #pragma unroll
        for (int kt = 0; kt < 4; kt++) {
            #pragma unroll
            for (int nt2 = 0; nt2 < 4; nt2++) {
                uint32_t Bh[4];
                int br = nt2 * 16 + bRowL;
                uint32_t bd = smb + W2_HI + br * 128 + ((kt * 32 + bCbL) ^ ((br & 7) << 4));
                ldsm4(Bh, bd);
                #pragma unroll
                for (int m = 0; m < 2; m++)
                    #pragma unroll
                    for (int p = 0; p < 2; p++)
                        mma_f16(C2[m][nt2 * 2 + p], A2h[m][kt], Bh[2 * p], Bh[2 * p + 1]);
            }
        }

        // ---- epi2: feat = relu(C2 + be2) fp32; float4 atomics; A3 fp16 frags ----
        uint32_t A3h[2][4][4];
        #pragma unroll
        for (int m = 0; m < 2; m++) {
            int rr0 = __shfl_sync(FULLM, rI, m * 16 + qr);
            int rr1 = __shfl_sync(FULLM, rI, m * 16 + 8 + qr);
            #pragma unroll
            for (int nt = 0; nt < 8; nt++) {
                int col0 = nt * 8 + q2;
                float2 bb = *(float2*)(sMisc + 64 + col0);
                float f0 = fmaxf(C2[m][nt][0] + bb.x, 0.f);
                float f1 = fmaxf(C2[m][nt][1] + bb.y, 0.f);
                float f2 = fmaxf(C2[m][nt][2] + bb.x, 0.f);
                float f3 = fmaxf(C2[m][nt][3] + bb.y, 0.f);
                int kt = nt >> 1, o = (nt & 1) * 2;
                A3h[m][kt][o]     = pack2h(f0, f1);
                A3h[m][kt][o + 1] = pack2h(f2, f3);
                float g0 = __shfl_xor_sync(FULLM, f0, 1);
                float g1 = __shfl_xor_sync(FULLM, f1, 1);
                float g2 = __shfl_xor_sync(FULLM, f2, 1);
                float g3 = __shfl_xor_sync(FULLM, f3, 1);
                if ((lane & 1) == 0) {
                    int cb = nt * 8 + ((lane & 3) >> 1) * 4;
                    if (rr0 >= 0)
                        atomicAdd((float4*)(g_agg_h + (size_t)rr0 * 64 + cb),
                                  make_float4(f0, f1, g0, g1));
                    if (rr1 >= 0)
                        atomicAdd((float4*)(g_agg_h + (size_t)rr1 * 64 + cb),
                                  make_float4(f2, f3, g2, g3));
                }
            }
        }

        // ================= GEMM3 (gate) =================
        float C3[2][8][4];
        #pragma unroll
        for (int m = 0; m < 2; m++)
            #pragma unroll
            for (int n = 0; n < 8; n++)
                #pragma unroll
                for (int k = 0; k < 4; k++) C3[m][n][k] = 0.f;
        #pragma unroll
        for (int kt = 0; kt < 4; kt++) {
            #pragma unroll
            for (int nt2 = 0; nt2 < 4; nt2++) {
                uint32_t Bh[4];
                int br = nt2 * 16 + bRowL;
                uint32_t bd = smb + WC_HI + br * 128 + ((kt * 32 + bCbL) ^ ((br & 7) << 4));
                ldsm4(Bh, bd);
                #pragma unroll
                for (int m = 0; m < 2; m++)
                    #pragma unroll
                    for (int p = 0; p < 2; p++)
                        mma_f16(C3[m][nt2 * 2 + p], A3h[m][kt], Bh[2 * p], Bh[2 * p + 1]);
            }
        }

        // ---- epi3 ----
        #pragma unroll
        for (int m = 0; m < 2; m++) {
            float p0 = 0.f, p1 = 0.f;
            #pragma unroll
            for (int nt = 0; nt < 8; nt++) {
                int col0 = nt * 8 + q2;
                float2 bb = *(float2*)(sMisc + 128 + col0);
                float2 w2 = *(float2*)(sMisc + 192 + col0);
                p0 += fmaxf(C3[m][nt][0] + bb.x, 0.f) * w2.x
                    + fmaxf(C3[m][nt][1] + bb.y, 0.f) * w2.y;
                p1 += fmaxf(C3[m][nt][2] + bb.x, 0.f) * w2.x
                    + fmaxf(C3[m][nt][3] + bb.y, 0.f) * w2.y;
            }
            p0 += __shfl_xor_sync(FULLM, p0, 1);
            p0 += __shfl_xor_sync(FULLM, p0, 2);
            p1 += __shfl_xor_sync(FULLM, p1, 1);
            p1 += __shfl_xor_sync(FULLM, p1, 2);

            int row0 = m * 16 + qr, row1 = row0 + 8;
            float gx0 = __shfl_sync(FULLM, dx, row0), gy0 = __shfl_sync(FULLM, dy, row0),
                  gz0 = __shfl_sync(FULLM, dz, row0);
            float gx1 = __shfl_sync(FULLM, dx, row1), gy1 = __shfl_sync(FULLM, dy, row1),
                  gz1 = __shfl_sync(FULLM, dz, row1);
            int r0v = __shfl_sync(FULLM, rI, row0);
            int r1v = __shfl_sync(FULLM, rI, row1);

            if ((lane & 3) == 0) {
                if (r0v >= 0) {
                    float gt = p0 + bc2v;
                    atomicAdd(&g_sum4[r0v], make_float4(
                        fminf(fmaxf(gx0 * gt, -100.f), 100.f),
                        fminf(fmaxf(gy0 * gt, -100.f), 100.f),
                        fminf(fmaxf(gz0 * gt, -100.f), 100.f), 1.f));
                }
                if (r1v >= 0) {
                    float gt = p1 + bc2v;
                    atomicAdd(&g_sum4[r1v], make_float4(
                        fminf(fmaxf(gx1 * gt, -100.f), 100.f),
                        fminf(fmaxf(gy1 * gt, -100.f), 100.f),
                        fminf(fmaxf(gz1 * gt, -100.f), 100.f), 1.f));
                }
            }
        }
    }
}

// ===========================================================================
// Node kernel: pure fp16 HMMA, 256 thr / 8 warps; coord fused at head
// ===========================================================================
#define NW2  16384
#define NMISC 24576
#define NA_OFF 25088
#define SMEM_N (NA_OFF + 8 * 4096)

__global__ __launch_bounds__(256, 1) void node_mma_kernel(
    const float* __restrict__ h,
    const float* __restrict__ coord, const float* __restrict__ vel,
    float* __restrict__ out_h, float* __restrict__ out_coord,
    float* __restrict__ out_v, int N)
{
    extern __shared__ char sm[];
    const uint32_t smb = smem_to_u32(sm);
    const int tid = threadIdx.x;
    float* sMisc = (float*)(sm + NMISC);

    for (int i = blockIdx.x * 256 + tid; i < N; i += gridDim.x * 256) {
        float4 s = g_sum4[i];
        float c = s.w;
        float invc = (c > 0.f) ? (1.f / fmaxf(c, 1.f)) : 0.f;
        float vx = vel[i * 3 + 0] + s.x * invc * 0.125f;
        float vy = vel[i * 3 + 1] + s.y * invc * 0.125f;
        float vz = vel[i * 3 + 2] + s.z * invc * 0.125f;
        out_v[i * 3 + 0] = vx;
        out_v[i * 3 + 1] = vy;
        out_v[i * 3 + 2] = vz;
        out_coord[i * 3 + 0] = coord[i * 3 + 0] + vx * 0.125f;
        out_coord[i * 3 + 1] = coord[i * 3 + 1] + vy * 0.125f;
        out_coord[i * 3 + 2] = coord[i * 3 + 2] + vz * 0.125f;
    }

    {
        const uint4* src = (const uint4*)g_packN;
        uint4* dst = (uint4*)sm;
        for (int i = tid; i < 1536; i += 256) dst[i] = src[i];    // 24576 B
        const uint4* ms = (const uint4*)(g_packN + 24576);
        uint4* md = (uint4*)(sm + NMISC);
        if (tid < 32) md[tid] = ms[tid];                          // 512 B
    }
    __syncthreads();

    const int warp = tid >> 5, lane = tid & 31;
    char* aPtr = sm + NA_OFF + warp * 4096;
    const uint32_t aHi = smb + NA_OFF + warp * 4096;

    const int aRowL = ((lane >> 3) & 1) * 8 + (lane & 7);
    const int aCbL  = ((lane >> 4) & 1) * 16;
    const int bRowL = ((lane >> 4) & 1) * 8 + (lane & 7);
    const int bCbL  = ((lane >> 3) & 1) * 16;
    const int q2 = (lane & 3) * 2;
    const int qr = lane >> 2;

    const int ntiles = (N + 31) >> 5;

    for (int t = blockIdx.x * 8 + warp; t < ntiles; t += gridDim.x * 8) {
        const int nbase = t << 5;

        float C[2][8][4];
        #pragma unroll
        for (int m = 0; m < 2; m++)
            #pragma unroll
            for (int n = 0; n < 8; n++)
                #pragma unroll
                for (int k = 0; k < 4; k++) C[m][n][k] = 0.f;

        #pragma unroll
        for (int half = 0; half < 2; half++) {
            __syncwarp();
            const float* src = half ? g_agg_h : h;
            #pragma unroll
            for (int i = 0; i < 16; i++) {
                int row = (i << 1) | (lane >> 4);
                int node = nbase + row;
                if (node >= N) node = N - 1;
                float4 v = *(const float4*)(src + (size_t)node * 64 + (lane & 15) * 4);
                uint32_t h0 = pack2h(v.x, v.y);
                uint32_t h1 = pack2h(v.z, v.w);
                uint32_t off = (uint32_t)(row * 128 + (((lane & 15) * 8) ^ ((row & 7) << 4)));
                *(uint2*)(aPtr + off) = make_uint2(h0, h1);
            }
            __syncwarp();

            const uint32_t wB = smb + (half ? 8192 : 0);
            #pragma unroll
            for (int kt = 0; kt < 4; kt++) {
                uint32_t Ah[2][4];
                #pragma unroll
                for (int m = 0; m < 2; m++) {
                    int ar = m * 16 + aRowL;
                    uint32_t ad = aHi + ar * 128 + ((kt * 32 + aCbL) ^ ((ar & 7) << 4));
                    ldsm4(Ah[m], ad);
                }
                #pragma unroll
                for (int nt2 = 0; nt2 < 4; nt2++) {
                    uint32_t Bh[4];
                    int br = nt2 * 16 + bRowL;
                    uint32_t bd = wB + br * 128 + ((kt * 32 + bCbL) ^ ((br & 7) << 4));
                    ldsm4(Bh, bd);
                    #pragma unroll
                    for (int m = 0; m < 2; m++)
                        #pragma unroll
                        for (int p = 0; p < 2; p++)
                            mma_f16(C[m][nt2 * 2 + p], Ah[m], Bh[2 * p], Bh[2 * p + 1]);
                }
            }
        }

        uint32_t A2h[2][4][4];
        #pragma unroll
        for (int m = 0; m < 2; m++) {
            #pragma unroll
            for (int nt = 0; nt < 8; nt++) {
                int col0 = nt * 8 + q2;
                float2 bb = *(float2*)(sMisc + col0);
                float c0 = fmaxf(C[m][nt][0] + bb.x, 0.f);
                float c1 = fmaxf(C[m][nt][1] + bb.y, 0.f);
                float c2 = fmaxf(C[m][nt][2] + bb.x, 0.f);
                float c3 = fmaxf(C[m][nt][3] + bb.y, 0.f);
                int kt = nt >> 1, o = (nt & 1) * 2;
                A2h[m][kt][o]     = pack2h(c0, c1);
                A2h[m][kt][o + 1] = pack2h(c2, c3);
            }
        }

        float C2[2][8][4];
        #pragma unroll
        for (int m = 0; m < 2; m++)
            #pragma unroll
            for (int n = 0; n < 8; n++)
                #pragma unroll
                for (int k = 0; k < 4; k++) C2[m][n][k] = 0.f;
        #pragma unroll
        for (int kt = 0; kt < 4; kt++) {
            #pragma unroll
            for (int nt2 = 0; nt2 < 4; nt2++) {
                uint32_t Bh[4];
                int br = nt2 * 16 + bRowL;
                uint32_t bd = smb + NW2 + br * 128 + ((kt * 32 + bCbL) ^ ((br & 7) << 4));
                ldsm4(Bh, bd);
                #pragma unroll
                for (int m = 0; m < 2; m++)
                    #pragma unroll
                    for (int p = 0; p < 2; p++)
                        mma_f16(C2[m][nt2 * 2 + p], A2h[m][kt], Bh[2 * p], Bh[2 * p + 1]);
            }
        }

        #pragma unroll
        for (int m = 0; m < 2; m++) {
            int row0 = nbase + m * 16 + qr;
            int row1 = row0 + 8;
            bool v0 = row0 < N, v1 = row1 < N;
            #pragma unroll
            for (int nt = 0; nt < 8; nt++) {
                int col0 = nt * 8 + q2;
                float2 bb = *(float2*)(sMisc + 64 + col0);
                if (v0) {
                    float2 rs = *(const float2*)(h + (size_t)row0 * 64 + col0);
                    float2 o = make_float2(C2[m][nt][0] + bb.x + rs.x,
                                           C2[m][nt][1] + bb.y + rs.y);
                    *(float2*)(out_h + (size_t)row0 * 64 + col0) = o;
                }
                if (v1) {
                    float2 rs = *(const float2*)(h + (size_t)row1 * 64 + col0);
                    float2 o = make_float2(C2[m][nt][2] + bb.x + rs.x,
                                           C2[m][nt][3] + bb.y + rs.y);
                    *(float2*)(out_h + (size_t)row1 * 64 + col0) = o;
                }
            }
        }
    }
}

// ---------------------------------------------------------------------------
extern "C" void kernel_launch(void* const* d_in, const int* in_sizes, int n_in,
                              void* d_out, int out_size)
{
    const float* h     = (const float*)d_in[0];
    const float* coord = (const float*)d_in[1];
    const float* vel   = (const float*)d_in[2];
    const int*   eidx  = (const int*)d_in[4];
    const float* We1 = (const float*)d_in[5];
    const float* be1 = (const float*)d_in[6];
    const float* We2 = (const float*)d_in[7];
    const float* be2 = (const float*)d_in[8];
    const float* Wn1 = (const float*)d_in[9];
    const float* bn1 = (const float*)d_in[10];
    const float* Wn2 = (const float*)d_in[11];
    const float* bn2 = (const float*)d_in[12];
    const float* Wc1 = (const float*)d_in[13];
    const float* bc1 = (const float*)d_in[14];
    const float* Wc2 = (const float*)d_in[15];
    const float* bc2 = (const float*)d_in[16];

    const int N = in_sizes[0] / 64;
    const int E = in_sizes[4] / 2;

    float* out       = (float*)d_out;
    float* out_h     = out;
    float* out_coord = out + (size_t)N * 64;
    float* out_v     = out_coord + (size_t)N * 3;

    cudaFuncSetAttribute(edge_mma_kernel, cudaFuncAttributeMaxDynamicSharedMemorySize, SMEM_E);
    cudaFuncSetAttribute(node_mma_kernel, cudaFuncAttributeMaxDynamicSharedMemorySize, SMEM_N);

    prep_kernel<<<512, 256>>>(N, We1, be1, We2, be2, Wc1, bc1, Wc2,
                              Wn1, bn1, Wn2, bn2);
    edge_mma_kernel<<<148, ETPB, SMEM_E>>>(h, coord, eidx, E, bc2);
    node_mma_kernel<<<148, 256, SMEM_N>>>(h, coord, vel,
                                          out_h, out_coord, out_v, N);
}

// round 13
// speedup vs baseline: 2.6665x; 1.0409x over previous
#include <cuda_runtime.h>
#include <cuda_fp16.h>
#include <cstdint>

typedef unsigned long long u64;
#define FULLM 0xffffffffu

#define NMAX 50048
__device__ float  g_agg_h[(size_t)NMAX * 64];
__device__ float4 g_sum4[NMAX];
// prepacked fp16 weight images (byte-identical to kernel smem layouts)
#define PACKE_BYTES 34048   // W1A 8K | W1B 8K | W2 8K | WC 8K | misc 1280
#define PACKN_BYTES 25088   // NW1A 8K | NW1B 8K | NW2 8K | misc 512
__device__ __align__(16) char g_packE[PACKE_BYTES];
__device__ __align__(16) char g_packN[PACKN_BYTES];

// ===========================================================================
// common helpers
// ===========================================================================
__device__ __forceinline__ uint32_t smem_to_u32(const void* p) {
    uint32_t a;
    asm("{ .reg .u64 t; cvta.to.shared.u64 t, %1; cvt.u32.u64 %0, t; }" : "=r"(a) : "l"(p));
    return a;
}
__device__ __forceinline__ void ldsm4(uint32_t r[4], uint32_t addr) {
    asm volatile("ldmatrix.sync.aligned.m8n8.x4.shared.b16 {%0,%1,%2,%3}, [%4];"
        : "=r"(r[0]), "=r"(r[1]), "=r"(r[2]), "=r"(r[3]) : "r"(addr));
}
__device__ __forceinline__ void mma_f16(float c[4], const uint32_t a[4],
                                        uint32_t b0, uint32_t b1) {
    asm volatile("mma.sync.aligned.m16n8k16.row.col.f32.f16.f16.f32 "
        "{%0,%1,%2,%3},{%4,%5,%6,%7},{%8,%9},{%0,%1,%2,%3};"
        : "+f"(c[0]), "+f"(c[1]), "+f"(c[2]), "+f"(c[3])
        : "r"(a[0]), "r"(a[1]), "r"(a[2]), "r"(a[3]), "r"(b0), "r"(b1));
}
__device__ __forceinline__ uint32_t pack2h(float a, float b) {
    __half2 hh = __floats2half2_rn(a, b);
    return *(uint32_t*)&hh;
}
__device__ __forceinline__ void putw16(char* base, int plane, int j, int k, float x) {
    __half hb = __float2half_rn(x);
    uint32_t off = (uint32_t)(j * 128 + ((k * 2) ^ ((j & 7) << 4)));
    *(__half*)(base + plane + off) = hb;
}

// ===========================================================================
// Prep kernel: zero accumulators + pack fp16 weight images
// ===========================================================================
__global__ void prep_kernel(int n,
    const float* __restrict__ We1, const float* __restrict__ be1,
    const float* __restrict__ We2, const float* __restrict__ be2,
    const float* __restrict__ Wc1, const float* __restrict__ bc1,
    const float* __restrict__ Wc2,
    const float* __restrict__ Wn1, const float* __restrict__ bn1,
    const float* __restrict__ Wn2, const float* __restrict__ bn2)
{
    int gid = blockIdx.x * blockDim.x + threadIdx.x;
    int stride = gridDim.x * blockDim.x;
    float4 z = make_float4(0.f, 0.f, 0.f, 0.f);
    for (int i = gid; i < n * 17; i += stride) {
        if (i < n * 16) ((float4*)g_agg_h)[i] = z;
        else            g_sum4[i - n * 16] = z;
    }
    float* miscE = (float*)(g_packE + 32768);
    float* miscN = (float*)(g_packN + 24576);
    if (gid < 129 * 64) {
        int k = gid >> 6, j = gid & 63;
        float x = We1[gid];
        if (k < 128) putw16(g_packE, (k < 64) ? 0 : 8192, j, k & 63, x);
        else         miscE[256 + j] = x;
    }
    if (gid < 64 * 64) {
        int k = gid >> 6, j = gid & 63;
        putw16(g_packE, 16384, j, k, We2[gid]);
        putw16(g_packE, 24576, j, k, Wc1[gid]);
        putw16(g_packN, 16384, j, k, Wn2[gid]);
    }
    if (gid < 128 * 64) {
        int k = gid >> 6, j = gid & 63;
        putw16(g_packN, (k < 64) ? 0 : 8192, j, k & 63, Wn1[gid]);
    }
    if (gid < 64)        { miscE[gid] = be1[gid];            miscN[gid] = bn1[gid]; }
    else if (gid < 128)  { miscE[gid] = be2[gid - 64];       miscN[gid] = bn2[gid - 64]; }
    else if (gid < 192)  { miscE[gid] = bc1[gid - 128]; }
    else if (gid < 256)  { miscE[gid] = Wc2[gid - 192]; }
}

// ===========================================================================
// Edge kernel: pure fp16 HMMA, 320 thr / 10 warps, bias folded into C-init
// ===========================================================================
#define ETPB 320
#define EWARPS 10
#define W1A_HI   0
#define W1B_HI   8192
#define W2_HI    16384
#define WC_HI    24576
#define A_OFF    32768                       // per warp 4096
#define MISC_OFF (A_OFF + EWARPS * 4096)     // 73728
#define SMEM_E   (MISC_OFF + 1280)

__global__ __launch_bounds__(ETPB, 1) void edge_mma_kernel(
    const float* __restrict__ h, const float* __restrict__ coord,
    const int* __restrict__ eidx, int E, const float* __restrict__ bc2)
{
    extern __shared__ char sm[];
    const uint32_t smb = smem_to_u32(sm);
    const int tid = threadIdx.x;
    float* sMisc = (float*)(sm + MISC_OFF);

    {
        const uint4* src = (const uint4*)g_packE;
        uint4* dst = (uint4*)sm;
        for (int i = tid; i < 2048; i += ETPB) dst[i] = src[i];
        const uint4* ms = (const uint4*)(g_packE + 32768);
        uint4* md = (uint4*)(sm + MISC_OFF);
        if (tid < 80) md[tid] = ms[tid];
    }
    const float bc2v = bc2[0];
    __syncthreads();

    const int warp = tid >> 5, lane = tid & 31;
    char* aPtr = sm + A_OFF + warp * 4096;
    const uint32_t aHi = smb + A_OFF + warp * 4096;

    const int aRowL = ((lane >> 3) & 1) * 8 + (lane & 7);
    const int aCbL  = ((lane >> 4) & 1) * 16;
    const int bRowL = ((lane >> 4) & 1) * 8 + (lane & 7);
    const int bCbL  = ((lane >> 3) & 1) * 16;
    const int q2 = (lane & 3) * 2;
    const int qr = lane >> 2;

    const int estride = gridDim.x * ETPB;

    for (int e0 = (blockIdx.x * EWARPS + warp) * 32; e0 < E; e0 += estride) {
        int e = e0 + lane;
        bool valid = e < E;
        int ec = valid ? e : (E - 1);
        int r = eidx[ec], cI = eidx[E + ec];
        float dx = coord[r * 3 + 0] - coord[cI * 3 + 0];
        float dy = coord[r * 3 + 1] - coord[cI * 3 + 1];
        float dz = coord[r * 3 + 2] - coord[cI * 3 + 2];
        float rad = valid ? (dx * dx + dy * dy + dz * dz) : 0.f;
        int rI = valid ? r : -1;

        // ---- C init = be1 + rad * w1rad (bias+radial folded) ----
        float C[2][8][4];
        #pragma unroll
        for (int m = 0; m < 2; m++) {
            float rad0 = __shfl_sync(FULLM, rad, m * 16 + qr);
            float rad1 = __shfl_sync(FULLM, rad, m * 16 + 8 + qr);
            #pragma unroll
            for (int nt = 0; nt < 8; nt++) {
                int col0 = nt * 8 + q2;
                float2 bb = *(float2*)(sMisc + col0);
                float2 wr = *(float2*)(sMisc + 256 + col0);
                C[m][nt][0] = fmaf(rad0, wr.x, bb.x);
                C[m][nt][1] = fmaf(rad0, wr.y, bb.y);
                C[m][nt][2] = fmaf(rad1, wr.x, bb.x);
                C[m][nt][3] = fmaf(rad1, wr.y, bb.y);
            }
        }

        // ================= GEMM1 =================
        #pragma unroll
        for (int half = 0; half < 2; half++) {
            __syncwarp();
            #pragma unroll
            for (int i = 0; i < 16; i++) {
                int edge = (i << 1) | (lane >> 4);
                int node = __shfl_sync(FULLM, half ? cI : r, edge);
                float4 v = *(const float4*)(h + (size_t)node * 64 + (lane & 15) * 4);
                uint32_t h0 = pack2h(v.x, v.y);
                uint32_t h1 = pack2h(v.z, v.w);
                uint32_t off = (uint32_t)(edge * 128 + (((lane & 15) * 8) ^ ((edge & 7) << 4)));
                *(uint2*)(aPtr + off) = make_uint2(h0, h1);
            }
            __syncwarp();

            const uint32_t wB = smb + (half ? W1B_HI : W1A_HI);
            #pragma unroll
            for (int kt = 0; kt < 4; kt++) {
                uint32_t Ah[2][4];
                #pragma unroll
                for (int m = 0; m < 2; m++) {
                    int ar = m * 16 + aRowL;
                    uint32_t ad = aHi + ar * 128 + ((kt * 32 + aCbL) ^ ((ar & 7) << 4));
                    ldsm4(Ah[m], ad);
                }
                #pragma unroll
                for (int nt2 = 0; nt2 < 4; nt2++) {
                    uint32_t Bh[4];
                    int br = nt2 * 16 + bRowL;
                    uint32_t bd = wB + br * 128 + ((kt * 32 + bCbL) ^ ((br & 7) << 4));
                    ldsm4(Bh, bd);
                    #pragma unroll
                    for (int m = 0; m < 2; m++)
                        #pragma unroll
                        for (int p = 0; p < 2; p++)
                            mma_f16(C[m][nt2 * 2 + p], Ah[m], Bh[2 * p], Bh[2 * p + 1]);
                }
            }
        }

        // ---- epi1: relu -> A2 fp16 frags; C2 init = be2 ----
        uint32_t A2h[2][4][4];
        float C2[2][8][4];
        #pragma unroll
        for (int nt = 0; nt < 8; nt++) {
            int col0 = nt * 8 + q2;
            float2 b2 = *(float2*)(sMisc + 64 + col0);
            #pragma unroll
            for (int m = 0; m < 2; m++) {
                float c0 = fmaxf(C[m][nt][0], 0.f);
                float c1 = fmaxf(C[m][nt][1], 0.f);
                float c2 = fmaxf(C[m][nt][2], 0.f);
                float c3 = fmaxf(C[m][nt][3], 0.f);
                int kt = nt >> 1, o = (nt & 1) * 2;
                A2h[m][kt][o]     = pack2h(c0, c1);
                A2h[m][kt][o + 1] = pack2h(c2, c3);
                C2[m][nt][0] = b2.x; C2[m][nt][1] = b2.y;
                C2[m][nt][2] = b2.x; C2[m][nt][3] = b2.y;
            }
        }

        // ================= GEMM2 =================
        #pragma unroll
        for (int kt = 0; kt < 4; kt++) {
            #pragma unroll
            for (int nt2 = 0; nt2 < 4; nt2++) {
                uint32_t Bh[4];
                int br = nt2 * 16 + bRowL;
                uint32_t bd = smb + W2_HI + br * 128 + ((kt * 32 + bCbL) ^ ((br & 7) << 4));
                ldsm4(Bh, bd);
                #pragma unroll
                for (int m = 0; m < 2; m++)
                    #pragma unroll
                    for (int p = 0; p < 2; p++)
                        mma_f16(C2[m][nt2 * 2 + p], A2h[m][kt], Bh[2 * p], Bh[2 * p + 1]);
            }
        }

        // ---- epi2: feat = relu(C2); atomics; A3 frags; C3 init = bc1 ----
        uint32_t A3h[2][4][4];
        float C3[2][8][4];
        #pragma unroll
        for (int m = 0; m < 2; m++) {
            int rr0 = __shfl_sync(FULLM, rI, m * 16 + qr);
            int rr1 = __shfl_sync(FULLM, rI, m * 16 + 8 + qr);
            #pragma unroll
            for (int nt = 0; nt < 8; nt++) {
                int col0 = nt * 8 + q2;
                float2 bc = *(float2*)(sMisc + 128 + col0);
                float f0 = fmaxf(C2[m][nt][0], 0.f);
                float f1 = fmaxf(C2[m][nt][1], 0.f);
                float f2 = fmaxf(C2[m][nt][2], 0.f);
                float f3 = fmaxf(C2[m][nt][3], 0.f);
                int kt = nt >> 1, o = (nt & 1) * 2;
                A3h[m][kt][o]     = pack2h(f0, f1);
                A3h[m][kt][o + 1] = pack2h(f2, f3);
                C3[m][nt][0] = bc.x; C3[m][nt][1] = bc.y;
                C3[m][nt][2] = bc.x; C3[m][nt][3] = bc.y;
                float g0 = __shfl_xor_sync(FULLM, f0, 1);
                float g1 = __shfl_xor_sync(FULLM, f1, 1);
                float g2 = __shfl_xor_sync(FULLM, f2, 1);
                float g3 = __shfl_xor_sync(FULLM, f3, 1);
                if ((lane & 1) == 0) {
                    int cb = nt * 8 + ((lane & 3) >> 1) * 4;
                    if (rr0 >= 0)
                        atomicAdd((float4*)(g_agg_h + (size_t)rr0 * 64 + cb),
                                  make_float4(f0, f1, g0, g1));
                    if (rr1 >= 0)
                        atomicAdd((float4*)(g_agg_h + (size_t)rr1 * 64 + cb),
                                  make_float4(f2, f3, g2, g3));
                }
            }
        }

        // ================= GEMM3 (gate) =================
        #pragma unroll
        for (int kt = 0; kt < 4; kt++) {
            #pragma unroll
            for (int nt2 = 0; nt2 < 4; nt2++) {
                uint32_t Bh[4];
                int br = nt2 * 16 + bRowL;
                uint32_t bd = smb + WC_HI + br * 128 + ((kt * 32 + bCbL) ^ ((br & 7) << 4));
                ldsm4(Bh, bd);
                #pragma unroll
                for (int m = 0; m < 2; m++)
                    #pragma unroll
                    for (int p = 0; p < 2; p++)
                        mma_f16(C3[m][nt2 * 2 + p], A3h[m][kt], Bh[2 * p], Bh[2 * p + 1]);
            }
        }

        // ---- epi3 ----
        #pragma unroll
        for (int m = 0; m < 2; m++) {
            float p0 = 0.f, p1 = 0.f;
            #pragma unroll
            for (int nt = 0; nt < 8; nt++) {
                int col0 = nt * 8 + q2;
                float2 w2 = *(float2*)(sMisc + 192 + col0);
                p0 += fmaxf(C3[m][nt][0], 0.f) * w2.x + fmaxf(C3[m][nt][1], 0.f) * w2.y;
                p1 += fmaxf(C3[m][nt][2], 0.f) * w2.x + fmaxf(C3[m][nt][3], 0.f) * w2.y;
            }
            p0 += __shfl_xor_sync(FULLM, p0, 1);
            p0 += __shfl_xor_sync(FULLM, p0, 2);
            p1 += __shfl_xor_sync(FULLM, p1, 1);
            p1 += __shfl_xor_sync(FULLM, p1, 2);

            int row0 = m * 16 + qr, row1 = row0 + 8;
            float gx0 = __shfl_sync(FULLM, dx, row0), gy0 = __shfl_sync(FULLM, dy, row0),
                  gz0 = __shfl_sync(FULLM, dz, row0);
            float gx1 = __shfl_sync(FULLM, dx, row1), gy1 = __shfl_sync(FULLM, dy, row1),
                  gz1 = __shfl_sync(FULLM, dz, row1);
            int r0v = __shfl_sync(FULLM, rI, row0);
            int r1v = __shfl_sync(FULLM, rI, row1);

            if ((lane & 3) == 0) {
                if (r0v >= 0) {
                    float gt = p0 + bc2v;
                    atomicAdd(&g_sum4[r0v], make_float4(
                        fminf(fmaxf(gx0 * gt, -100.f), 100.f),
                        fminf(fmaxf(gy0 * gt, -100.f), 100.f),
                        fminf(fmaxf(gz0 * gt, -100.f), 100.f), 1.f));
                }
                if (r1v >= 0) {
                    float gt = p1 + bc2v;
                    atomicAdd(&g_sum4[r1v], make_float4(
                        fminf(fmaxf(gx1 * gt, -100.f), 100.f),
                        fminf(fmaxf(gy1 * gt, -100.f), 100.f),
                        fminf(fmaxf(gz1 * gt, -100.f), 100.f), 1.f));
                }
            }
        }
    }
}

// ===========================================================================
// Node kernel: pure fp16 HMMA, 256 thr / 8 warps, grid 196 (1 tile/warp)
// ===========================================================================
#define NW2  16384
#define NMISC 24576
#define NA_OFF 25088
#define SMEM_N (NA_OFF + 8 * 4096)

__global__ __launch_bounds__(256, 1) void node_mma_kernel(
    const float* __restrict__ h,
    const float* __restrict__ coord, const float* __restrict__ vel,
    float* __restrict__ out_h, float* __restrict__ out_coord,
    float* __restrict__ out_v, int N)
{
    extern __shared__ char sm[];
    const uint32_t smb = smem_to_u32(sm);
    const int tid = threadIdx.x;
    float* sMisc = (float*)(sm + NMISC);

    for (int i = blockIdx.x * 256 + tid; i < N; i += gridDim.x * 256) {
        float4 s = g_sum4[i];
        float c = s.w;
        float invc = (c > 0.f) ? (1.f / fmaxf(c, 1.f)) : 0.f;
        float vx = vel[i * 3 + 0] + s.x * invc * 0.125f;
        float vy = vel[i * 3 + 1] + s.y * invc * 0.125f;
        float vz = vel[i * 3 + 2] + s.z * invc * 0.125f;
        out_v[i * 3 + 0] = vx;
        out_v[i * 3 + 1] = vy;
        out_v[i * 3 + 2] = vz;
        out_coord[i * 3 + 0] = coord[i * 3 + 0] + vx * 0.125f;
        out_coord[i * 3 + 1] = coord[i * 3 + 1] + vy * 0.125f;
        out_coord[i * 3 + 2] = coord[i * 3 + 2] + vz * 0.125f;
    }

    {
        const uint4* src = (const uint4*)g_packN;
        uint4* dst = (uint4*)sm;
        for (int i = tid; i < 1536; i += 256) dst[i] = src[i];
        const uint4* ms = (const uint4*)(g_packN + 24576);
        uint4* md = (uint4*)(sm + NMISC);
        if (tid < 32) md[tid] = ms[tid];
    }
    __syncthreads();

    const int warp = tid >> 5, lane = tid & 31;
    char* aPtr = sm + NA_OFF + warp * 4096;
    const uint32_t aHi = smb + NA_OFF + warp * 4096;

    const int aRowL = ((lane >> 3) & 1) * 8 + (lane & 7);
    const int aCbL  = ((lane >> 4) & 1) * 16;
    const int bRowL = ((lane >> 4) & 1) * 8 + (lane & 7);
    const int bCbL  = ((lane >> 3) & 1) * 16;
    const int q2 = (lane & 3) * 2;
    const int qr = lane >> 2;

    const int ntiles = (N + 31) >> 5;

    for (int t = blockIdx.x * 8 + warp; t < ntiles; t += gridDim.x * 8) {
        const int nbase = t << 5;

        // ---- C init = bn1 ----
        float C[2][8][4];
        #pragma unroll
        for (int nt = 0; nt < 8; nt++) {
            int col0 = nt * 8 + q2;
            float2 bb = *(float2*)(sMisc + col0);
            #pragma unroll
            for (int m = 0; m < 2; m++) {
                C[m][nt][0] = bb.x; C[m][nt][1] = bb.y;
                C[m][nt][2] = bb.x; C[m][nt][3] = bb.y;
            }
        }

        #pragma unroll
        for (int half = 0; half < 2; half++) {
            __syncwarp();
            const float* src = half ? g_agg_h : h;
            #pragma unroll
            for (int i = 0; i < 16; i++) {
                int row = (i << 1) | (lane >> 4);
                int node = nbase + row;
                if (node >= N) node = N - 1;
                float4 v = *(const float4*)(src + (size_t)node * 64 + (lane & 15) * 4);
                uint32_t h0 = pack2h(v.x, v.y);
                uint32_t h1 = pack2h(v.z, v.w);
                uint32_t off = (uint32_t)(row * 128 + (((lane & 15) * 8) ^ ((row & 7) << 4)));
                *(uint2*)(aPtr + off) = make_uint2(h0, h1);
            }
            __syncwarp();

            const uint32_t wB = smb + (half ? 8192 : 0);
            #pragma unroll
            for (int kt = 0; kt < 4; kt++) {
                uint32_t Ah[2][4];
                #pragma unroll
                for (int m = 0; m < 2; m++) {
                    int ar = m * 16 + aRowL;
                    uint32_t ad = aHi + ar * 128 + ((kt * 32 + aCbL) ^ ((ar & 7) << 4));
                    ldsm4(Ah[m], ad);
                }
                #pragma unroll
                for (int nt2 = 0; nt2 < 4; nt2++) {
                    uint32_t Bh[4];
                    int br = nt2 * 16 + bRowL;
                    uint32_t bd = wB + br * 128 + ((kt * 32 + bCbL) ^ ((br & 7) << 4));
                    ldsm4(Bh, bd);
                    #pragma unroll
                    for (int m = 0; m < 2; m++)
                        #pragma unroll
                        for (int p = 0; p < 2; p++)
                            mma_f16(C[m][nt2 * 2 + p], Ah[m], Bh[2 * p], Bh[2 * p + 1]);
                }
            }
        }

        // ---- epi1: relu -> A2 frags; C2 init = bn2 ----
        uint32_t A2h[2][4][4];
        float C2[2][8][4];
        #pragma unroll
        for (int nt = 0; nt < 8; nt++) {
            int col0 = nt * 8 + q2;
            float2 b2 = *(float2*)(sMisc + 64 + col0);
            #pragma unroll
            for (int m = 0; m < 2; m++) {
                float c0 = fmaxf(C[m][nt][0], 0.f);
                float c1 = fmaxf(C[m][nt][1], 0.f);
                float c2 = fmaxf(C[m][nt][2], 0.f);
                float c3 = fmaxf(C[m][nt][3], 0.f);
                int kt = nt >> 1, o = (nt & 1) * 2;
                A2h[m][kt][o]     = pack2h(c0, c1);
                A2h[m][kt][o + 1] = pack2h(c2, c3);
                C2[m][nt][0] = b2.x; C2[m][nt][1] = b2.y;
                C2[m][nt][2] = b2.x; C2[m][nt][3] = b2.y;
            }
        }

        #pragma unroll
        for (int kt = 0; kt < 4; kt++) {
            #pragma unroll
            for (int nt2 = 0; nt2 < 4; nt2++) {
                uint32_t Bh[4];
                int br = nt2 * 16 + bRowL;
                uint32_t bd = smb + NW2 + br * 128 + ((kt * 32 + bCbL) ^ ((br & 7) << 4));
                ldsm4(Bh, bd);
                #pragma unroll
                for (int m = 0; m < 2; m++)
                    #pragma unroll
                    for (int p = 0; p < 2; p++)
                        mma_f16(C2[m][nt2 * 2 + p], A2h[m][kt], Bh[2 * p], Bh[2 * p + 1]);
            }
        }

        #pragma unroll
        for (int m = 0; m < 2; m++) {
            int row0 = nbase + m * 16 + qr;
            int row1 = row0 + 8;
            bool v0 = row0 < N, v1 = row1 < N;
            #pragma unroll
            for (int nt = 0; nt < 8; nt++) {
                int col0 = nt * 8 + q2;
                if (v0) {
                    float2 rs = *(const float2*)(h + (size_t)row0 * 64 + col0);
                    float2 o = make_float2(C2[m][nt][0] + rs.x, C2[m][nt][1] + rs.y);
                    *(float2*)(out_h + (size_t)row0 * 64 + col0) = o;
                }
                if (v1) {
                    float2 rs = *(const float2*)(h + (size_t)row1 * 64 + col0);
                    float2 o = make_float2(C2[m][nt][2] + rs.x, C2[m][nt][3] + rs.y);
                    *(float2*)(out_h + (size_t)row1 * 64 + col0) = o;
                }
            }
        }
    }
}

// ---------------------------------------------------------------------------
extern "C" void kernel_launch(void* const* d_in, const int* in_sizes, int n_in,
                              void* d_out, int out_size)
{
    const float* h     = (const float*)d_in[0];
    const float* coord = (const float*)d_in[1];
    const float* vel   = (const float*)d_in[2];
    const int*   eidx  = (const int*)d_in[4];
    const float* We1 = (const float*)d_in[5];
    const float* be1 = (const float*)d_in[6];
    const float* We2 = (const float*)d_in[7];
    const float* be2 = (const float*)d_in[8];
    const float* Wn1 = (const float*)d_in[9];
    const float* bn1 = (const float*)d_in[10];
    const float* Wn2 = (const float*)d_in[11];
    const float* bn2 = (const float*)d_in[12];
    const float* Wc1 = (const float*)d_in[13];
    const float* bc1 = (const float*)d_in[14];
    const float* Wc2 = (const float*)d_in[15];
    const float* bc2 = (const float*)d_in[16];

    const int N = in_sizes[0] / 64;
    const int E = in_sizes[4] / 2;

    float* out       = (float*)d_out;
    float* out_h     = out;
    float* out_coord = out + (size_t)N * 64;
    float* out_v     = out_coord + (size_t)N * 3;

    cudaFuncSetAttribute(edge_mma_kernel, cudaFuncAttributeMaxDynamicSharedMemorySize, SMEM_E);
    cudaFuncSetAttribute(node_mma_kernel, cudaFuncAttributeMaxDynamicSharedMemorySize, SMEM_N);

    prep_kernel<<<512, 256>>>(N, We1, be1, We2, be2, Wc1, bc1, Wc2,
                              Wn1, bn1, Wn2, bn2);
    edge_mma_kernel<<<148, ETPB, SMEM_E>>>(h, coord, eidx, E, bc2);
    node_mma_kernel<<<196, 256, SMEM_N>>>(h, coord, vel,
                                          out_h, out_coord, out_v, N);
}